// round 1
// baseline (speedup 1.0000x reference)
#include <cuda_runtime.h>
#include <cstdint>

// Problem constants
#define BS_  128
#define NE_  512
#define NQ_  128
#define EMB_ 512
#define H_   8
#define HD_  64
#define F3_  1536   // 3 * EMB

// Scratch (allocation-free rule: __device__ globals)
__device__ float g_qkv[(size_t)BS_ * NE_ * F3_];     // 402 MB: [b*NE+n][f]
__device__ float g_attn[(size_t)BS_ * NQ_ * EMB_];   // 33.5 MB: [b*NQ+q][h*64+d]
__device__ int   g_mask_i32;                         // 1 if masks are int32, 0 if uint8

// ---------------------------------------------------------------------------
// Mask dtype detection: jax bool masks may arrive as int32 (0/1) or uint8.
// If int32 little-endian with values {0,1}, bytes 4g+1..3 are always zero.
// With ~50% random 1-bytes, a uint8 layout violates that within a few groups.
// Deterministic for fixed inputs -> graph-safe.
// ---------------------------------------------------------------------------
__global__ void detect_mask_kernel(const unsigned char* __restrict__ p) {
    if (threadIdx.x == 0) {
        int i32 = 1;
        for (int g = 0; g < 256; g++) {
            if (p[4 * g + 1] | p[4 * g + 2] | p[4 * g + 3]) { i32 = 0; break; }
        }
        g_mask_i32 = i32;
    }
}

__device__ __forceinline__ int mask_at(const unsigned char* __restrict__ p,
                                       int idx, int i32) {
    // int32 little-endian: LSB (the 0/1 value) lives at byte 4*idx
    return (int)p[i32 ? (idx << 2) : idx];
}

// ---------------------------------------------------------------------------
// GEMM: C[M,N] = A[M,K] * B[N,K]^T   (both operands K-major row-major)
// 128x128 CTA tile, BK=16, 256 threads, 8x8 register micro-tile.
// ---------------------------------------------------------------------------
__global__ __launch_bounds__(256) void gemm_qkv(
    const float* __restrict__ A, const float* __restrict__ B,
    float* __restrict__ C, int M, int N, int K)
{
    __shared__ float As[16][128];
    __shared__ float Bs[16][128];
    const int tid = threadIdx.x;
    const int bm  = blockIdx.y * 128;
    const int bn  = blockIdx.x * 128;
    const int tx  = tid & 15;
    const int ty  = tid >> 4;

    float acc[8][8];
#pragma unroll
    for (int i = 0; i < 8; i++)
#pragma unroll
        for (int j = 0; j < 8; j++) acc[i][j] = 0.f;

    for (int k0 = 0; k0 < K; k0 += 16) {
#pragma unroll
        for (int it = 0; it < 2; it++) {
            int idx = tid + it * 256;          // 0..511
            int r   = idx >> 2;                // 0..127
            int c4  = idx & 3;                 // 0..3 (float4 group along K)
            float4 va = *(const float4*)&A[(size_t)(bm + r) * K + k0 + c4 * 4];
            As[c4 * 4 + 0][r] = va.x; As[c4 * 4 + 1][r] = va.y;
            As[c4 * 4 + 2][r] = va.z; As[c4 * 4 + 3][r] = va.w;
            float4 vb = *(const float4*)&B[(size_t)(bn + r) * K + k0 + c4 * 4];
            Bs[c4 * 4 + 0][r] = vb.x; Bs[c4 * 4 + 1][r] = vb.y;
            Bs[c4 * 4 + 2][r] = vb.z; Bs[c4 * 4 + 3][r] = vb.w;
        }
        __syncthreads();
#pragma unroll
        for (int kk = 0; kk < 16; kk++) {
            float a[8], b[8];
            *(float4*)&a[0] = *(const float4*)&As[kk][ty * 8];
            *(float4*)&a[4] = *(const float4*)&As[kk][ty * 8 + 4];
            *(float4*)&b[0] = *(const float4*)&Bs[kk][tx * 8];
            *(float4*)&b[4] = *(const float4*)&Bs[kk][tx * 8 + 4];
#pragma unroll
            for (int i = 0; i < 8; i++)
#pragma unroll
                for (int j = 0; j < 8; j++)
                    acc[i][j] = fmaf(a[i], b[j], acc[i][j]);
        }
        __syncthreads();
    }

#pragma unroll
    for (int i = 0; i < 8; i++) {
        size_t row = (size_t)(bm + ty * 8 + i);
        float4 c0 = make_float4(acc[i][0], acc[i][1], acc[i][2], acc[i][3]);
        float4 c1 = make_float4(acc[i][4], acc[i][5], acc[i][6], acc[i][7]);
        *(float4*)&C[row * N + bn + tx * 8]     = c0;
        *(float4*)&C[row * N + bn + tx * 8 + 4] = c1;
    }
}

// ---------------------------------------------------------------------------
// Output GEMM with epilogue: out = attn @ W_out^T + b_out, post-mask zeroing.
// ---------------------------------------------------------------------------
__global__ __launch_bounds__(256) void gemm_out(
    const float* __restrict__ A, const float* __restrict__ B,
    const float* __restrict__ bias, const unsigned char* __restrict__ post,
    float* __restrict__ C, int M, int N, int K)
{
    __shared__ float As[16][128];
    __shared__ float Bs[16][128];
    const int tid = threadIdx.x;
    const int bm  = blockIdx.y * 128;
    const int bn  = blockIdx.x * 128;
    const int tx  = tid & 15;
    const int ty  = tid >> 4;
    const int i32 = g_mask_i32;

    float acc[8][8];
#pragma unroll
    for (int i = 0; i < 8; i++)
#pragma unroll
        for (int j = 0; j < 8; j++) acc[i][j] = 0.f;

    for (int k0 = 0; k0 < K; k0 += 16) {
#pragma unroll
        for (int it = 0; it < 2; it++) {
            int idx = tid + it * 256;
            int r   = idx >> 2;
            int c4  = idx & 3;
            float4 va = *(const float4*)&A[(size_t)(bm + r) * K + k0 + c4 * 4];
            As[c4 * 4 + 0][r] = va.x; As[c4 * 4 + 1][r] = va.y;
            As[c4 * 4 + 2][r] = va.z; As[c4 * 4 + 3][r] = va.w;
            float4 vb = *(const float4*)&B[(size_t)(bn + r) * K + k0 + c4 * 4];
            Bs[c4 * 4 + 0][r] = vb.x; Bs[c4 * 4 + 1][r] = vb.y;
            Bs[c4 * 4 + 2][r] = vb.z; Bs[c4 * 4 + 3][r] = vb.w;
        }
        __syncthreads();
#pragma unroll
        for (int kk = 0; kk < 16; kk++) {
            float a[8], b[8];
            *(float4*)&a[0] = *(const float4*)&As[kk][ty * 8];
            *(float4*)&a[4] = *(const float4*)&As[kk][ty * 8 + 4];
            *(float4*)&b[0] = *(const float4*)&Bs[kk][tx * 8];
            *(float4*)&b[4] = *(const float4*)&Bs[kk][tx * 8 + 4];
#pragma unroll
            for (int i = 0; i < 8; i++)
#pragma unroll
                for (int j = 0; j < 8; j++)
                    acc[i][j] = fmaf(a[i], b[j], acc[i][j]);
        }
        __syncthreads();
    }

    float bv[8];
#pragma unroll
    for (int j = 0; j < 8; j++) bv[j] = bias[bn + tx * 8 + j];

#pragma unroll
    for (int i = 0; i < 8; i++) {
        int row = bm + ty * 8 + i;
        float keep = (mask_at(post, row, i32) == 0) ? 1.f : 0.f;
        float4 c0 = make_float4((acc[i][0] + bv[0]) * keep, (acc[i][1] + bv[1]) * keep,
                                (acc[i][2] + bv[2]) * keep, (acc[i][3] + bv[3]) * keep);
        float4 c1 = make_float4((acc[i][4] + bv[4]) * keep, (acc[i][5] + bv[5]) * keep,
                                (acc[i][6] + bv[6]) * keep, (acc[i][7] + bv[7]) * keep);
        *(float4*)&C[(size_t)row * N + bn + tx * 8]     = c0;
        *(float4*)&C[(size_t)row * N + bn + tx * 8 + 4] = c1;
    }
}

// ---------------------------------------------------------------------------
// Fused attention: one CTA per (batch, head), thread t = query t.
// Single pass, no max-subtraction (logits bounded |l| < ~2 by construction).
// w_i = e_i*d_i / (T + 1e-8*S),  e_i = valid_i * exp(l_i), S=sum e, T=sum e*d
// (exactly equal to softmax -> NaN->0 -> *diff -> renorm(+1e-8) chain).
// ---------------------------------------------------------------------------
__global__ __launch_bounds__(128) void attn_kernel(
    const float* __restrict__ qkv,
    const unsigned char* __restrict__ pre,
    const float* __restrict__ diff,
    float* __restrict__ attn)
{
    __shared__ float k_s[32][64];
    __shared__ float v_s[32][64];
    __shared__ float diff_s[128][33];
    __shared__ unsigned char valid_s[128][36];

    const int b = blockIdx.x;
    const int h = blockIdx.y;
    const int t = threadIdx.x;   // query index
    const int i32 = g_mask_i32;

    // q for this (b, t, h): 64 floats into registers
    float qr[64];
    {
        const float* qrow = &qkv[((size_t)b * NE_ + t) * F3_ + h * HD_];
#pragma unroll
        for (int d4 = 0; d4 < 16; d4++) {
            float4 v = *(const float4*)&qrow[d4 * 4];
            qr[d4 * 4 + 0] = v.x; qr[d4 * 4 + 1] = v.y;
            qr[d4 * 4 + 2] = v.z; qr[d4 * 4 + 3] = v.w;
        }
    }

    float acc[64];
#pragma unroll
    for (int d = 0; d < 64; d++) acc[d] = 0.f;
    float S = 0.f, T = 0.f;

    for (int kt = 0; kt < NE_; kt += 32) {
        __syncthreads();
        // K/V tiles: 32 keys x 64 dims, float4 cooperative load
#pragma unroll
        for (int it = 0; it < 4; it++) {
            int idx = t + it * 128;           // 0..511
            int j   = idx >> 4;               // key row 0..31
            int c4  = idx & 15;               // float4 column
            const float* base =
                &qkv[((size_t)b * NE_ + kt + j) * F3_ + h * HD_ + c4 * 4];
            ((float4*)k_s[j])[c4] = *(const float4*)(base + EMB_);
            ((float4*)v_s[j])[c4] = *(const float4*)(base + 2 * EMB_);
        }
        // masks: 128 queries x 32 keys
#pragma unroll
        for (int it = 0; it < 32; it++) {
            int idx = t + it * 128;           // 0..4095
            int q   = idx >> 5;
            int j   = idx & 31;
            int midx = (b * NQ_ + q) * NE_ + kt + j;
            valid_s[q][j] = (unsigned char)(mask_at(pre, midx, i32) == 0);
            diff_s[q][j]  = diff[midx];
        }
        __syncthreads();

#pragma unroll 4
        for (int j = 0; j < 32; j++) {
            const float4* k4 = (const float4*)k_s[j];
            float l = 0.f;
#pragma unroll
            for (int d4 = 0; d4 < 16; d4++) {
                float4 kv = k4[d4];
                l = fmaf(qr[d4 * 4 + 0], kv.x, l);
                l = fmaf(qr[d4 * 4 + 1], kv.y, l);
                l = fmaf(qr[d4 * 4 + 2], kv.z, l);
                l = fmaf(qr[d4 * 4 + 3], kv.w, l);
            }
            float e  = __expf(l * 0.125f) * (float)valid_s[t][j];
            float ed = e * diff_s[t][j];
            S += e;
            T += ed;
            const float4* v4 = (const float4*)v_s[j];
#pragma unroll
            for (int d4 = 0; d4 < 16; d4++) {
                float4 vv = v4[d4];
                acc[d4 * 4 + 0] = fmaf(ed, vv.x, acc[d4 * 4 + 0]);
                acc[d4 * 4 + 1] = fmaf(ed, vv.y, acc[d4 * 4 + 1]);
                acc[d4 * 4 + 2] = fmaf(ed, vv.z, acc[d4 * 4 + 2]);
                acc[d4 * 4 + 3] = fmaf(ed, vv.w, acc[d4 * 4 + 3]);
            }
        }
    }

    float inv = (S > 0.f) ? (1.f / (T + 1e-8f * S)) : 0.f;
    float* orow = &attn[((size_t)b * NQ_ + t) * EMB_ + h * HD_];
#pragma unroll
    for (int d4 = 0; d4 < 16; d4++) {
        float4 o = make_float4(acc[d4 * 4 + 0] * inv, acc[d4 * 4 + 1] * inv,
                               acc[d4 * 4 + 2] * inv, acc[d4 * 4 + 3] * inv);
        *(float4*)&orow[d4 * 4] = o;
    }
}

// ---------------------------------------------------------------------------
// Launch: inputs in setup_inputs() order:
// 0 entities (128,512,512) f32 | 1 pre_mask (128,128,512) bool
// 2 diff_mask (128,128,512) f32 | 3 post_mask (128,128) bool
// 4 W_in (1536,512) f32 | 5 W_out (512,512) f32 | 6 b_out (512,) f32
// ---------------------------------------------------------------------------
extern "C" void kernel_launch(void* const* d_in, const int* in_sizes, int n_in,
                              void* d_out, int out_size) {
    const float* entities        = (const float*)d_in[0];
    const unsigned char* pre     = (const unsigned char*)d_in[1];
    const float* diff            = (const float*)d_in[2];
    const unsigned char* post    = (const unsigned char*)d_in[3];
    const float* W_in            = (const float*)d_in[4];
    const float* W_out           = (const float*)d_in[5];
    const float* b_out           = (const float*)d_in[6];
    float* out                   = (float*)d_out;

    float* qkv = nullptr;
    float* attn = nullptr;
    cudaGetSymbolAddress((void**)&qkv, g_qkv);
    cudaGetSymbolAddress((void**)&attn, g_attn);

    detect_mask_kernel<<<1, 32>>>(pre);

    // qkv = entities @ W_in^T : M=65536, N=1536, K=512
    gemm_qkv<<<dim3(F3_ / 128, (BS_ * NE_) / 128), 256>>>(
        entities, W_in, qkv, BS_ * NE_, F3_, 512);

    // fused attention: one CTA per (b, h)
    attn_kernel<<<dim3(BS_, H_), 128>>>(qkv, pre, diff, attn);

    // out = attn @ W_out^T + b_out, post-masked : M=16384, N=512, K=512
    gemm_out<<<dim3(EMB_ / 128, (BS_ * NQ_) / 128), 256>>>(
        attn, W_out, b_out, post, out, BS_ * NQ_, EMB_, EMB_);
}

// round 4
// speedup vs baseline: 2.1774x; 2.1774x over previous
#include <cuda_runtime.h>
#include <cstdint>

// Problem constants
#define BS_  128
#define NE_  512
#define NQ_  128
#define EMB_ 512
#define H_   8
#define HD_  64
#define F3_  1536

// Scratch (allocation-free rule: __device__ globals)
__device__ float g_qkv[(size_t)BS_ * NE_ * F3_];
__device__ float g_attn[(size_t)BS_ * NQ_ * EMB_];
__device__ int   g_mask_i32;

// ---------------------------------------------------------------------------
// Mask dtype detection (jax bool may arrive as int32 or uint8)
// ---------------------------------------------------------------------------
__global__ void detect_mask_kernel(const unsigned char* __restrict__ p) {
    if (threadIdx.x == 0) {
        int i32 = 1;
        for (int g = 0; g < 256; g++) {
            if (p[4 * g + 1] | p[4 * g + 2] | p[4 * g + 3]) { i32 = 0; break; }
        }
        g_mask_i32 = i32;
    }
}
__device__ __forceinline__ int mask_at(const unsigned char* __restrict__ p,
                                       int idx, int i32) {
    return (int)p[i32 ? (idx << 2) : idx];
}

// ---------------------------------------------------------------------------
// tf32 helpers (plain sm_103-legal PTX: mma.sync + cvt.rna)
// ---------------------------------------------------------------------------
__device__ __forceinline__ uint32_t f2tf32(float f) {
    uint32_t u;
    asm("cvt.rna.tf32.f32 %0, %1;" : "=r"(u) : "f"(f));
    return u;
}

#define MMA_TF32(d, a, b)                                                     \
    asm volatile(                                                             \
        "mma.sync.aligned.m16n8k8.row.col.f32.tf32.tf32.f32 "                 \
        "{%0,%1,%2,%3}, {%4,%5,%6,%7}, {%8,%9}, {%0,%1,%2,%3};"               \
        : "+f"((d)[0]), "+f"((d)[1]), "+f"((d)[2]), "+f"((d)[3])              \
        : "r"((a)[0]), "r"((a)[1]), "r"((a)[2]), "r"((a)[3]),                 \
          "r"((b)[0]), "r"((b)[1]))

// ---------------------------------------------------------------------------
// tf32 tensor-core GEMM: C[.., ldc] slice = A[M,512] * B[N,512]^T
// CTA tile 128x256, BK=32, 256 threads, 2x4 warp grid of 64x64 warp tiles.
// Double-buffered smem (pad 36 words/row -> conflict-free frag loads),
// register prefetch of the next k-slab while computing the current one.
// remap: row m -> (m>>7)*512 + (m&127)  (first 128 rows of each batch)
// epi:   + bias, post-mask zeroing
// ---------------------------------------------------------------------------
#define AW   4608                     // 128*36 words per A buffer
#define BW   9216                     // 256*36 words per B buffer
#define BUFW (AW + BW)
#define GEMM_SMEM (2 * BUFW * 4)      // 110592 bytes

__global__ __launch_bounds__(256, 1) void gemm_mma(
    const float* __restrict__ A, const float* __restrict__ B,
    float* __restrict__ C, int ldc, int col_off, int remap, int epi,
    const float* __restrict__ bias, const unsigned char* __restrict__ post)
{
    extern __shared__ uint32_t sm[];
    const int tid  = threadIdx.x;
    const int lane = tid & 31;
    const int warp = tid >> 5;
    const int gid  = lane >> 2;       // 0..7
    const int tg   = lane & 3;        // 0..3
    const int wm   = warp >> 2;       // 0..1
    const int wn   = warp & 3;        // 0..3
    const int bm   = blockIdx.y * 128;
    const int bn   = blockIdx.x * 256;

    float acc[4][8][4];
#pragma unroll
    for (int mi = 0; mi < 4; mi++)
#pragma unroll
        for (int ni = 0; ni < 8; ni++)
#pragma unroll
            for (int r = 0; r < 4; r++) acc[mi][ni][r] = 0.f;

    float pa[16], pb[32];

    // ---- prologue: load k-slab 0, convert, store to buffer 0 ----
#pragma unroll
    for (int i = 0; i < 4; i++) {
        int idx = tid + i * 256, r = idx >> 3, c4 = idx & 7;
        int ga = bm + r;
        if (remap) ga = ((ga >> 7) << 9) | (ga & 127);
        *(float4*)&pa[i * 4] = *(const float4*)&A[(size_t)ga * 512 + c4 * 4];
    }
#pragma unroll
    for (int i = 0; i < 8; i++) {
        int idx = tid + i * 256, r = idx >> 3, c4 = idx & 7;
        *(float4*)&pb[i * 4] = *(const float4*)&B[(size_t)(bn + r) * 512 + c4 * 4];
    }
#pragma unroll
    for (int i = 0; i < 4; i++) {
        int idx = tid + i * 256, r = idx >> 3, c4 = idx & 7;
        uint32_t* d = &sm[r * 36 + c4 * 4];
        d[0] = f2tf32(pa[i*4+0]); d[1] = f2tf32(pa[i*4+1]);
        d[2] = f2tf32(pa[i*4+2]); d[3] = f2tf32(pa[i*4+3]);
    }
#pragma unroll
    for (int i = 0; i < 8; i++) {
        int idx = tid + i * 256, r = idx >> 3, c4 = idx & 7;
        uint32_t* d = &sm[AW + r * 36 + c4 * 4];
        d[0] = f2tf32(pb[i*4+0]); d[1] = f2tf32(pb[i*4+1]);
        d[2] = f2tf32(pb[i*4+2]); d[3] = f2tf32(pb[i*4+3]);
    }
    __syncthreads();

#pragma unroll 1
    for (int kt = 0; kt < 16; kt++) {
        // ---- prefetch next k-slab into registers ----
        if (kt + 1 < 16) {
            const int k0 = (kt + 1) * 32;
#pragma unroll
            for (int i = 0; i < 4; i++) {
                int idx = tid + i * 256, r = idx >> 3, c4 = idx & 7;
                int ga = bm + r;
                if (remap) ga = ((ga >> 7) << 9) | (ga & 127);
                *(float4*)&pa[i * 4] =
                    *(const float4*)&A[(size_t)ga * 512 + k0 + c4 * 4];
            }
#pragma unroll
            for (int i = 0; i < 8; i++) {
                int idx = tid + i * 256, r = idx >> 3, c4 = idx & 7;
                *(float4*)&pb[i * 4] =
                    *(const float4*)&B[(size_t)(bn + r) * 512 + k0 + c4 * 4];
            }
        }

        // ---- compute current buffer ----
        const uint32_t* Ab = sm + (kt & 1) * BUFW;
        const uint32_t* Bb = Ab + AW;
#pragma unroll
        for (int ks = 0; ks < 4; ks++) {
            const int k0 = ks * 8;
            uint32_t af[4][4], bf[8][2];
#pragma unroll
            for (int mi = 0; mi < 4; mi++) {
                int r0 = (wm * 64 + mi * 16 + gid) * 36 + k0 + tg;
                af[mi][0] = Ab[r0];
                af[mi][1] = Ab[r0 + 8 * 36];
                af[mi][2] = Ab[r0 + 4];
                af[mi][3] = Ab[r0 + 8 * 36 + 4];
            }
#pragma unroll
            for (int ni = 0; ni < 8; ni++) {
                int n0 = (wn * 64 + ni * 8 + gid) * 36 + k0 + tg;
                bf[ni][0] = Bb[n0];
                bf[ni][1] = Bb[n0 + 4];
            }
#pragma unroll
            for (int mi = 0; mi < 4; mi++)
#pragma unroll
                for (int ni = 0; ni < 8; ni++)
                    MMA_TF32(acc[mi][ni], af[mi], bf[ni]);
        }

        // ---- convert + store next slab, flip ----
        if (kt + 1 < 16) {
            uint32_t* An = sm + ((kt + 1) & 1) * BUFW;
            uint32_t* Bn = An + AW;
#pragma unroll
            for (int i = 0; i < 4; i++) {
                int idx = tid + i * 256, r = idx >> 3, c4 = idx & 7;
                uint32_t* d = &An[r * 36 + c4 * 4];
                d[0] = f2tf32(pa[i*4+0]); d[1] = f2tf32(pa[i*4+1]);
                d[2] = f2tf32(pa[i*4+2]); d[3] = f2tf32(pa[i*4+3]);
            }
#pragma unroll
            for (int i = 0; i < 8; i++) {
                int idx = tid + i * 256, r = idx >> 3, c4 = idx & 7;
                uint32_t* d = &Bn[r * 36 + c4 * 4];
                d[0] = f2tf32(pb[i*4+0]); d[1] = f2tf32(pb[i*4+1]);
                d[2] = f2tf32(pb[i*4+2]); d[3] = f2tf32(pb[i*4+3]);
            }
            __syncthreads();
        }
    }

    // ---- epilogue ----
    const int i32 = g_mask_i32;
#pragma unroll
    for (int mi = 0; mi < 4; mi++) {
        int rbase = bm + wm * 64 + mi * 16 + gid;
#pragma unroll
        for (int half = 0; half < 2; half++) {
            int row  = rbase + half * 8;
            int grow = remap ? (((row >> 7) << 9) | (row & 127)) : row;
            float keep = 1.f;
            if (epi) keep = (mask_at(post, grow, i32) == 0) ? 1.f : 0.f;
            float* crow = &C[(size_t)grow * ldc + col_off];
#pragma unroll
            for (int ni = 0; ni < 8; ni++) {
                int col = bn + wn * 64 + ni * 8 + 2 * tg;
                float v0 = acc[mi][ni][half * 2 + 0];
                float v1 = acc[mi][ni][half * 2 + 1];
                if (epi) {
                    v0 = (v0 + bias[col])     * keep;
                    v1 = (v1 + bias[col + 1]) * keep;
                }
                float2 o = make_float2(v0, v1);
                *(float2*)&crow[col] = o;
            }
        }
    }
}

// ---------------------------------------------------------------------------
// Fused attention (unchanged, passing since R1): one CTA per (batch, head).
// w_i = e_i*d_i / (T + 1e-8*S),  e_i = valid_i * exp(l_i)
// ---------------------------------------------------------------------------
__global__ __launch_bounds__(128) void attn_kernel(
    const float* __restrict__ qkv,
    const unsigned char* __restrict__ pre,
    const float* __restrict__ diff,
    float* __restrict__ attn)
{
    __shared__ float k_s[32][64];
    __shared__ float v_s[32][64];
    __shared__ float diff_s[128][33];
    __shared__ unsigned char valid_s[128][36];

    const int b = blockIdx.x;
    const int h = blockIdx.y;
    const int t = threadIdx.x;
    const int i32 = g_mask_i32;

    float qr[64];
    {
        const float* qrow = &qkv[((size_t)b * NE_ + t) * F3_ + h * HD_];
#pragma unroll
        for (int d4 = 0; d4 < 16; d4++) {
            float4 v = *(const float4*)&qrow[d4 * 4];
            qr[d4 * 4 + 0] = v.x; qr[d4 * 4 + 1] = v.y;
            qr[d4 * 4 + 2] = v.z; qr[d4 * 4 + 3] = v.w;
        }
    }

    float acc[64];
#pragma unroll
    for (int d = 0; d < 64; d++) acc[d] = 0.f;
    float S = 0.f, T = 0.f;

    for (int kt = 0; kt < NE_; kt += 32) {
        __syncthreads();
#pragma unroll
        for (int it = 0; it < 4; it++) {
            int idx = t + it * 128;
            int j   = idx >> 4;
            int c4  = idx & 15;
            const float* base =
                &qkv[((size_t)b * NE_ + kt + j) * F3_ + h * HD_ + c4 * 4];
            ((float4*)k_s[j])[c4] = *(const float4*)(base + EMB_);
            ((float4*)v_s[j])[c4] = *(const float4*)(base + 2 * EMB_);
        }
#pragma unroll
        for (int it = 0; it < 32; it++) {
            int idx = t + it * 128;
            int q   = idx >> 5;
            int j   = idx & 31;
            int midx = (b * NQ_ + q) * NE_ + kt + j;
            valid_s[q][j] = (unsigned char)(mask_at(pre, midx, i32) == 0);
            diff_s[q][j]  = diff[midx];
        }
        __syncthreads();

#pragma unroll 4
        for (int j = 0; j < 32; j++) {
            const float4* k4 = (const float4*)k_s[j];
            float l = 0.f;
#pragma unroll
            for (int d4 = 0; d4 < 16; d4++) {
                float4 kv = k4[d4];
                l = fmaf(qr[d4 * 4 + 0], kv.x, l);
                l = fmaf(qr[d4 * 4 + 1], kv.y, l);
                l = fmaf(qr[d4 * 4 + 2], kv.z, l);
                l = fmaf(qr[d4 * 4 + 3], kv.w, l);
            }
            float e  = __expf(l * 0.125f) * (float)valid_s[t][j];
            float ed = e * diff_s[t][j];
            S += e;
            T += ed;
            const float4* v4 = (const float4*)v_s[j];
#pragma unroll
            for (int d4 = 0; d4 < 16; d4++) {
                float4 vv = v4[d4];
                acc[d4 * 4 + 0] = fmaf(ed, vv.x, acc[d4 * 4 + 0]);
                acc[d4 * 4 + 1] = fmaf(ed, vv.y, acc[d4 * 4 + 1]);
                acc[d4 * 4 + 2] = fmaf(ed, vv.z, acc[d4 * 4 + 2]);
                acc[d4 * 4 + 3] = fmaf(ed, vv.w, acc[d4 * 4 + 3]);
            }
        }
    }

    float inv = (S > 0.f) ? (1.f / (T + 1e-8f * S)) : 0.f;
    float* orow = &attn[((size_t)b * NQ_ + t) * EMB_ + h * HD_];
#pragma unroll
    for (int d4 = 0; d4 < 16; d4++) {
        float4 o = make_float4(acc[d4 * 4 + 0] * inv, acc[d4 * 4 + 1] * inv,
                               acc[d4 * 4 + 2] * inv, acc[d4 * 4 + 3] * inv);
        *(float4*)&orow[d4 * 4] = o;
    }
}

// ---------------------------------------------------------------------------
// Launch
// ---------------------------------------------------------------------------
extern "C" void kernel_launch(void* const* d_in, const int* in_sizes, int n_in,
                              void* d_out, int out_size) {
    const float* entities     = (const float*)d_in[0];
    const unsigned char* pre  = (const unsigned char*)d_in[1];
    const float* diff         = (const float*)d_in[2];
    const unsigned char* post = (const unsigned char*)d_in[3];
    const float* W_in         = (const float*)d_in[4];
    const float* W_out        = (const float*)d_in[5];
    const float* b_out        = (const float*)d_in[6];
    float* out                = (float*)d_out;

    float* qkv = nullptr;
    float* attn = nullptr;
    cudaGetSymbolAddress((void**)&qkv, g_qkv);
    cudaGetSymbolAddress((void**)&attn, g_attn);

    cudaFuncSetAttribute(gemm_mma, cudaFuncAttributeMaxDynamicSharedMemorySize,
                         GEMM_SMEM);

    detect_mask_kernel<<<1, 32>>>(pre);

    // KV: qkv[:, 512:1536] = entities @ W_in[512:,:]^T  (M=65536, N=1024)
    gemm_mma<<<dim3(4, 512), 256, GEMM_SMEM>>>(
        entities, W_in + 512 * 512, qkv, F3_, 512, 0, 0, nullptr, nullptr);

    // Q: first 128 rows per batch (M=16384 remapped, N=512)
    gemm_mma<<<dim3(2, 128), 256, GEMM_SMEM>>>(
        entities, W_in, qkv, F3_, 0, 1, 0, nullptr, nullptr);

    // fused attention
    attn_kernel<<<dim3(BS_, H_), 128>>>(qkv, pre, diff, attn);

    // out = attn @ W_out^T + b_out, post-masked (M=16384, N=512)
    gemm_mma<<<dim3(2, 128), 256, GEMM_SMEM>>>(
        attn, W_out, out, EMB_, 0, 0, 1, b_out, post);
}

// round 6
// speedup vs baseline: 2.2734x; 1.0441x over previous
#include <cuda_runtime.h>
#include <cuda_fp16.h>
#include <cstdint>

// Problem constants
#define BS_  128
#define NE_  512
#define NQ_  128
#define EMB_ 512
#define H_   8
#define HD_  64
#define F3_  1536

// Scratch (allocation-free rule: __device__ globals)
__device__ float  g_qkv[(size_t)BS_ * NE_ * F3_];        // fp32 qkv for attention
__device__ __half g_ent_h[(size_t)BS_ * NE_ * 512];      // half entities
__device__ __half g_win_h[(size_t)F3_ * 512];            // half W_in
__device__ __half g_wout_h[(size_t)EMB_ * EMB_];         // half W_out
__device__ __half g_attn_h[(size_t)BS_ * NQ_ * EMB_];    // half attention output
__device__ int    g_mask_i32;

// ---------------------------------------------------------------------------
// Mask dtype detection (jax bool may arrive as int32 or uint8)
// ---------------------------------------------------------------------------
__global__ void detect_mask_kernel(const unsigned char* __restrict__ p) {
    if (threadIdx.x == 0) {
        int i32 = 1;
        for (int g = 0; g < 256; g++) {
            if (p[4 * g + 1] | p[4 * g + 2] | p[4 * g + 3]) { i32 = 0; break; }
        }
        g_mask_i32 = i32;
    }
}
__device__ __forceinline__ int mask_at(const unsigned char* __restrict__ p,
                                       int idx, int i32) {
    return (int)p[i32 ? (idx << 2) : idx];
}

// ---------------------------------------------------------------------------
// fp32 -> fp16 bulk convert (vectorized, grid-stride)
// ---------------------------------------------------------------------------
__global__ void cvt_f2h(const float4* __restrict__ src, uint2* __restrict__ dst,
                        int n4) {
    for (int i = blockIdx.x * blockDim.x + threadIdx.x; i < n4;
         i += gridDim.x * blockDim.x) {
        float4 v = src[i];
        __half2 a = __floats2half2_rn(v.x, v.y);
        __half2 b = __floats2half2_rn(v.z, v.w);
        uint2 o;
        o.x = *(uint32_t*)&a;
        o.y = *(uint32_t*)&b;
        dst[i] = o;
    }
}

// ---------------------------------------------------------------------------
// PTX helpers
// ---------------------------------------------------------------------------
__device__ __forceinline__ uint32_t smem_u32(const void* p) {
    uint32_t a;
    asm("{ .reg .u64 t; cvta.to.shared.u64 t, %1; cvt.u32.u64 %0, t; }"
        : "=r"(a) : "l"(p));
    return a;
}
#define CP_ASYNC16(dst, src) \
    asm volatile("cp.async.cg.shared.global [%0], [%1], 16;" \
                 :: "r"(dst), "l"(src) : "memory")
#define CP_COMMIT() asm volatile("cp.async.commit_group;" ::: "memory")
#define CP_WAIT0()  asm volatile("cp.async.wait_group 0;" ::: "memory")
#define CP_WAIT1()  asm volatile("cp.async.wait_group 1;" ::: "memory")

#define LDMATRIX_X4(r0, r1, r2, r3, addr) \
    asm volatile("ldmatrix.sync.aligned.m8n8.x4.shared.b16 {%0,%1,%2,%3}, [%4];" \
                 : "=r"(r0), "=r"(r1), "=r"(r2), "=r"(r3) : "r"(addr))

#define MMA_F16(d, a0, a1, a2, a3, b0, b1)                                    \
    asm volatile(                                                             \
        "mma.sync.aligned.m16n8k16.row.col.f32.f16.f16.f32 "                  \
        "{%0,%1,%2,%3}, {%4,%5,%6,%7}, {%8,%9}, {%0,%1,%2,%3};"               \
        : "+f"((d)[0]), "+f"((d)[1]), "+f"((d)[2]), "+f"((d)[3])              \
        : "r"(a0), "r"(a1), "r"(a2), "r"(a3), "r"(b0), "r"(b1))

// smem tile layout: row r (64B of 32 halves), 16B chunk c with XOR swizzle
__device__ __forceinline__ uint32_t swz(int r, int c) {
    return (uint32_t)(r * 64 + ((c ^ ((r >> 1) & 3)) << 4));
}

// ---------------------------------------------------------------------------
// fp16 tensor-core GEMM: C[., ldc] slice = A[M,512] * B[N,512]^T  (fp32 out)
// CTA 128x256, BK=32, 256 thr, 2x4 warps of 64x64 tiles; cp.async double buf.
// remap: A/C row m -> (m>>7)*512 + (m&127);  epi: +bias, post-mask zero.
// B fragment: [N,K] row-major IS col-major KxN -> NON-trans ldmatrix (R5 bug).
// ---------------------------------------------------------------------------
#define ABUF_B 8192                     // 128 rows * 64B
#define BBUF_B 16384                    // 256 rows * 64B
#define BUF_B  (ABUF_B + BBUF_B)
#define GEMM_SMEM (2 * BUF_B)           // 49152

__global__ __launch_bounds__(256, 1) void gemm_h(
    const __half* __restrict__ A, const __half* __restrict__ B,
    float* __restrict__ C, int ldc, int col_off, int remap, int epi,
    const float* __restrict__ bias, const unsigned char* __restrict__ post)
{
    extern __shared__ char smem[];
    const uint32_t sb = smem_u32(smem);
    const int tid  = threadIdx.x;
    const int lane = tid & 31;
    const int warp = tid >> 5;
    const int gid  = lane >> 2;
    const int tg   = lane & 3;
    const int wm   = warp >> 2;        // 0..1
    const int wn   = warp & 3;         // 0..3
    const int bm   = blockIdx.y * 128;
    const int bn   = blockIdx.x * 256;

    // producer indices: A 2 chunks/thread, B 4 chunks/thread
    const int pr  = tid >> 2;          // 0..63
    const int pc  = tid & 3;           // chunk 0..3

    float acc[4][8][4];
#pragma unroll
    for (int mi = 0; mi < 4; mi++)
#pragma unroll
        for (int ni = 0; ni < 8; ni++)
#pragma unroll
            for (int r = 0; r < 4; r++) acc[mi][ni][r] = 0.f;

    // ldmatrix lane address components
    // A x4: m0=rows0-7/k0-7, m1=rows8-15/k0-7, m2=rows0-7/k8-15, m3=rows8-15/k8-15
    const int a_roff = (lane & 7) + ((lane >> 3) & 1) * 8;
    const int a_coff = lane >> 4;                 // 0/1 (k chunk)
    // B x4 (non-trans): m0=n0-7/k0-7(b0 lo), m1=n0-7/k8-15(b1 lo),
    //                   m2=n8-15/k0-7(b0 hi), m3=n8-15/k8-15(b1 hi)
    const int b_noff = (lane & 7) + (lane >> 4) * 8;
    const int b_coff = (lane >> 3) & 1;

    // ---- producer ----
#define ISSUE(kt, buf) do {                                                   \
        const uint32_t ab = sb + (buf) * BUF_B;                               \
        const uint32_t bb = ab + ABUF_B;                                      \
        _Pragma("unroll")                                                     \
        for (int s = 0; s < 2; s++) {                                         \
            int r = pr + s * 64;                                              \
            int ga = bm + r;                                                  \
            if (remap) ga = ((ga >> 7) << 9) | (ga & 127);                    \
            CP_ASYNC16(ab + swz(r, pc),                                       \
                       &A[(size_t)ga * 512 + (kt) * 32 + pc * 8]);            \
        }                                                                     \
        _Pragma("unroll")                                                     \
        for (int s = 0; s < 4; s++) {                                         \
            int r = pr + s * 64;                                              \
            CP_ASYNC16(bb + swz(r, pc),                                       \
                       &B[(size_t)(bn + r) * 512 + (kt) * 32 + pc * 8]);      \
        }                                                                     \
        CP_COMMIT();                                                          \
    } while (0)

    ISSUE(0, 0);

#pragma unroll 1
    for (int kt = 0; kt < 16; kt++) {
        const int buf = kt & 1;
        if (kt < 15) { ISSUE(kt + 1, buf ^ 1); CP_WAIT1(); }
        else         { CP_WAIT0(); }
        __syncthreads();

        const uint32_t ab = sb + buf * BUF_B;
        const uint32_t bb = ab + ABUF_B;
#pragma unroll
        for (int ks = 0; ks < 2; ks++) {
            uint32_t af[4][4], bf[4][4];
#pragma unroll
            for (int mi = 0; mi < 4; mi++)
                LDMATRIX_X4(af[mi][0], af[mi][1], af[mi][2], af[mi][3],
                            ab + swz(wm * 64 + mi * 16 + a_roff,
                                     2 * ks + a_coff));
#pragma unroll
            for (int ni2 = 0; ni2 < 4; ni2++)
                LDMATRIX_X4(bf[ni2][0], bf[ni2][1], bf[ni2][2], bf[ni2][3],
                            bb + swz(wn * 64 + ni2 * 16 + b_noff,
                                     2 * ks + b_coff));
#pragma unroll
            for (int mi = 0; mi < 4; mi++)
#pragma unroll
                for (int ni2 = 0; ni2 < 4; ni2++) {
                    MMA_F16(acc[mi][2 * ni2],
                            af[mi][0], af[mi][1], af[mi][2], af[mi][3],
                            bf[ni2][0], bf[ni2][1]);
                    MMA_F16(acc[mi][2 * ni2 + 1],
                            af[mi][0], af[mi][1], af[mi][2], af[mi][3],
                            bf[ni2][2], bf[ni2][3]);
                }
        }
        __syncthreads();
    }
#undef ISSUE

    // ---- epilogue (fp32 out, optional bias + post-mask) ----
    const int i32 = g_mask_i32;
#pragma unroll
    for (int mi = 0; mi < 4; mi++) {
        int rbase = bm + wm * 64 + mi * 16 + gid;
#pragma unroll
        for (int half = 0; half < 2; half++) {
            int row  = rbase + half * 8;
            int grow = remap ? (((row >> 7) << 9) | (row & 127)) : row;
            float keep = 1.f;
            if (epi) keep = (mask_at(post, grow, i32) == 0) ? 1.f : 0.f;
            float* crow = &C[(size_t)grow * ldc + col_off];
#pragma unroll
            for (int ni = 0; ni < 8; ni++) {
                int col = bn + wn * 64 + ni * 8 + 2 * tg;
                float v0 = acc[mi][ni][half * 2 + 0];
                float v1 = acc[mi][ni][half * 2 + 1];
                if (epi) {
                    v0 = (v0 + bias[col])     * keep;
                    v1 = (v1 + bias[col + 1]) * keep;
                }
                *(float2*)&crow[col] = make_float2(v0, v1);
            }
        }
    }
}

// ---------------------------------------------------------------------------
// Fused attention, split-D: 256 threads, thread (q = tid>>1, hf = tid&1)
// owns 32 of the 64 head dims. Logit completed via shfl_xor(.,1).
// w_i = e_i*d_i / (T + 1e-8*S),  e_i = valid_i * exp(l_i)
// Writes half output for the fp16 out-projection GEMM.
// ---------------------------------------------------------------------------
__global__ __launch_bounds__(256) void attn_kernel(
    const float* __restrict__ qkv,
    const unsigned char* __restrict__ pre,
    const float* __restrict__ diff,
    __half* __restrict__ attn_h)
{
    __shared__ float k_s[32][64];
    __shared__ float v_s[32][64];
    __shared__ float diff_s[128][33];
    __shared__ unsigned char valid_s[128][36];

    const int b   = blockIdx.x;
    const int h   = blockIdx.y;
    const int tid = threadIdx.x;
    const int t   = tid >> 1;          // query
    const int hf  = tid & 1;           // head-dim half
    const int i32 = g_mask_i32;

    float qr[32];
    {
        const float* qrow = &qkv[((size_t)b * NE_ + t) * F3_ + h * HD_ + hf * 32];
#pragma unroll
        for (int d4 = 0; d4 < 8; d4++) {
            float4 v = *(const float4*)&qrow[d4 * 4];
            qr[d4 * 4 + 0] = v.x; qr[d4 * 4 + 1] = v.y;
            qr[d4 * 4 + 2] = v.z; qr[d4 * 4 + 3] = v.w;
        }
    }

    float acc[32];
#pragma unroll
    for (int d = 0; d < 32; d++) acc[d] = 0.f;
    float S = 0.f, T = 0.f;

    for (int kt = 0; kt < NE_; kt += 32) {
        __syncthreads();
#pragma unroll
        for (int it = 0; it < 2; it++) {
            int idx = tid + it * 256;        // 0..511
            int j   = idx >> 4;
            int c4  = idx & 15;
            const float* base =
                &qkv[((size_t)b * NE_ + kt + j) * F3_ + h * HD_ + c4 * 4];
            ((float4*)k_s[j])[c4] = *(const float4*)(base + EMB_);
            ((float4*)v_s[j])[c4] = *(const float4*)(base + 2 * EMB_);
        }
#pragma unroll
        for (int it = 0; it < 16; it++) {
            int idx = tid + it * 256;        // 0..4095
            int q   = idx >> 5;
            int j   = idx & 31;
            int midx = (b * NQ_ + q) * NE_ + kt + j;
            valid_s[q][j] = (unsigned char)(mask_at(pre, midx, i32) == 0);
            diff_s[q][j]  = diff[midx];
        }
        __syncthreads();

#pragma unroll 4
        for (int j = 0; j < 32; j++) {
            const float4* k4 = (const float4*)&k_s[j][hf * 32];
            float l = 0.f;
#pragma unroll
            for (int d4 = 0; d4 < 8; d4++) {
                float4 kv = k4[d4];
                l = fmaf(qr[d4 * 4 + 0], kv.x, l);
                l = fmaf(qr[d4 * 4 + 1], kv.y, l);
                l = fmaf(qr[d4 * 4 + 2], kv.z, l);
                l = fmaf(qr[d4 * 4 + 3], kv.w, l);
            }
            l += __shfl_xor_sync(0xFFFFFFFFu, l, 1);
            float e  = __expf(l * 0.125f) * (float)valid_s[t][j];
            float ed = e * diff_s[t][j];
            S += e;
            T += ed;
            const float4* v4 = (const float4*)&v_s[j][hf * 32];
#pragma unroll
            for (int d4 = 0; d4 < 8; d4++) {
                float4 vv = v4[d4];
                acc[d4 * 4 + 0] = fmaf(ed, vv.x, acc[d4 * 4 + 0]);
                acc[d4 * 4 + 1] = fmaf(ed, vv.y, acc[d4 * 4 + 1]);
                acc[d4 * 4 + 2] = fmaf(ed, vv.z, acc[d4 * 4 + 2]);
                acc[d4 * 4 + 3] = fmaf(ed, vv.w, acc[d4 * 4 + 3]);
            }
        }
    }

    float inv = (S > 0.f) ? (1.f / (T + 1e-8f * S)) : 0.f;
    __half* orow = &attn_h[((size_t)b * NQ_ + t) * EMB_ + h * HD_ + hf * 32];
#pragma unroll
    for (int d4 = 0; d4 < 8; d4++) {
        __half2 o = __floats2half2_rn(acc[d4 * 4 + 0] * inv,
                                      acc[d4 * 4 + 1] * inv);
        __half2 p = __floats2half2_rn(acc[d4 * 4 + 2] * inv,
                                      acc[d4 * 4 + 3] * inv);
        uint2 w;
        w.x = *(uint32_t*)&o;
        w.y = *(uint32_t*)&p;
        *(uint2*)&orow[d4 * 4] = w;
    }
}

// ---------------------------------------------------------------------------
// Launch
// ---------------------------------------------------------------------------
extern "C" void kernel_launch(void* const* d_in, const int* in_sizes, int n_in,
                              void* d_out, int out_size) {
    const float* entities     = (const float*)d_in[0];
    const unsigned char* pre  = (const unsigned char*)d_in[1];
    const float* diff         = (const float*)d_in[2];
    const unsigned char* post = (const unsigned char*)d_in[3];
    const float* W_in         = (const float*)d_in[4];
    const float* W_out        = (const float*)d_in[5];
    const float* b_out        = (const float*)d_in[6];
    float* out                = (float*)d_out;

    float*  qkv   = nullptr;
    __half* ent_h = nullptr;
    __half* win_h = nullptr;
    __half* wout_h = nullptr;
    __half* attn_h = nullptr;
    cudaGetSymbolAddress((void**)&qkv,    g_qkv);
    cudaGetSymbolAddress((void**)&ent_h,  g_ent_h);
    cudaGetSymbolAddress((void**)&win_h,  g_win_h);
    cudaGetSymbolAddress((void**)&wout_h, g_wout_h);
    cudaGetSymbolAddress((void**)&attn_h, g_attn_h);

    cudaFuncSetAttribute(gemm_h, cudaFuncAttributeMaxDynamicSharedMemorySize,
                         GEMM_SMEM);

    detect_mask_kernel<<<1, 32>>>(pre);

    // fp32 -> fp16 input conversions
    {
        int n4 = (BS_ * NE_ * 512) / 4;
        cvt_f2h<<<8192, 256>>>((const float4*)entities, (uint2*)ent_h, n4);
        n4 = (F3_ * 512) / 4;
        cvt_f2h<<<1024, 256>>>((const float4*)W_in, (uint2*)win_h, n4);
        n4 = (EMB_ * EMB_) / 4;
        cvt_f2h<<<512, 256>>>((const float4*)W_out, (uint2*)wout_h, n4);
    }

    // KV: qkv[:, 512:1536] = entities @ W_in[512:,:]^T  (M=65536, N=1024)
    gemm_h<<<dim3(4, 512), 256, GEMM_SMEM>>>(
        ent_h, win_h + 512 * 512, qkv, F3_, 512, 0, 0, nullptr, nullptr);

    // Q: first 128 rows per batch (M=16384 remapped, N=512)
    gemm_h<<<dim3(2, 128), 256, GEMM_SMEM>>>(
        ent_h, win_h, qkv, F3_, 0, 1, 0, nullptr, nullptr);

    // fused attention -> half output
    attn_kernel<<<dim3(BS_, H_), 256>>>(qkv, pre, diff, attn_h);

    // out = attn @ W_out^T + b_out, post-masked (M=16384, N=512)
    gemm_h<<<dim3(2, 128), 256, GEMM_SMEM>>>(
        attn_h, wout_h, out, EMB_, 0, 0, 1, b_out, post);
}

// round 8
// speedup vs baseline: 6.2706x; 2.7582x over previous
#include <cuda_runtime.h>
#include <cuda_fp16.h>
#include <cstdint>

// Problem constants
#define BS_  128
#define NE_  512
#define NQ_  128
#define EMB_ 512
#define H_   8
#define HD_  64
#define F3_  1536

// Scratch (allocation-free rule: __device__ globals)
__device__ __half g_qkv_h[(size_t)BS_ * NE_ * F3_];      // fp16 qkv
__device__ __half g_ent_h[(size_t)BS_ * NE_ * 512];      // half entities
__device__ __half g_win_h[(size_t)F3_ * 512];            // half W_in
__device__ __half g_wout_h[(size_t)EMB_ * EMB_];         // half W_out
__device__ __half g_attn_h[(size_t)BS_ * NQ_ * EMB_];    // half attention output
__device__ int    g_mask_i32;

// ---------------------------------------------------------------------------
// Mask dtype detection (jax bool may arrive as int32 or uint8)
// ---------------------------------------------------------------------------
__global__ void detect_mask_kernel(const unsigned char* __restrict__ p) {
    if (threadIdx.x == 0) {
        int i32 = 1;
        for (int g = 0; g < 256; g++) {
            if (p[4 * g + 1] | p[4 * g + 2] | p[4 * g + 3]) { i32 = 0; break; }
        }
        g_mask_i32 = i32;
    }
}
__device__ __forceinline__ int mask_at(const unsigned char* __restrict__ p,
                                       int idx, int i32) {
    return (int)p[i32 ? (idx << 2) : idx];
}
// valid = (mask == 0) for 2 consecutive indices (idx even)
__device__ __forceinline__ void valid2(const unsigned char* __restrict__ p,
                                       int idx, int i32, float& v0, float& v1) {
    if (i32) {
        int2 q = *(const int2*)(p + ((size_t)idx << 2));
        v0 = q.x ? 0.f : 1.f;
        v1 = q.y ? 0.f : 1.f;
    } else {
        unsigned short s = *(const unsigned short*)(p + idx);
        v0 = (s & 0xFF) ? 0.f : 1.f;
        v1 = (s >> 8)   ? 0.f : 1.f;
    }
}

// ---------------------------------------------------------------------------
// fp32 -> fp16 bulk convert
// ---------------------------------------------------------------------------
__global__ void cvt_f2h(const float4* __restrict__ src, uint2* __restrict__ dst,
                        int n4) {
    for (int i = blockIdx.x * blockDim.x + threadIdx.x; i < n4;
         i += gridDim.x * blockDim.x) {
        float4 v = src[i];
        __half2 a = __floats2half2_rn(v.x, v.y);
        __half2 b = __floats2half2_rn(v.z, v.w);
        uint2 o;
        o.x = *(uint32_t*)&a;
        o.y = *(uint32_t*)&b;
        dst[i] = o;
    }
}

// ---------------------------------------------------------------------------
// PTX helpers
// ---------------------------------------------------------------------------
__device__ __forceinline__ uint32_t smem_u32(const void* p) {
    uint32_t a;
    asm("{ .reg .u64 t; cvta.to.shared.u64 t, %1; cvt.u32.u64 %0, t; }"
        : "=r"(a) : "l"(p));
    return a;
}
#define CP_ASYNC16(dst, src) \
    asm volatile("cp.async.cg.shared.global [%0], [%1], 16;" \
                 :: "r"(dst), "l"(src) : "memory")
#define CP_COMMIT() asm volatile("cp.async.commit_group;" ::: "memory")
#define CP_WAIT0()  asm volatile("cp.async.wait_group 0;" ::: "memory")
#define CP_WAIT1()  asm volatile("cp.async.wait_group 1;" ::: "memory")

#define LDMATRIX_X4(r0, r1, r2, r3, addr) \
    asm volatile("ldmatrix.sync.aligned.m8n8.x4.shared.b16 {%0,%1,%2,%3}, [%4];" \
                 : "=r"(r0), "=r"(r1), "=r"(r2), "=r"(r3) : "r"(addr))
#define LDMATRIX_X4_T(r0, r1, r2, r3, addr) \
    asm volatile("ldmatrix.sync.aligned.m8n8.x4.trans.shared.b16 {%0,%1,%2,%3}, [%4];" \
                 : "=r"(r0), "=r"(r1), "=r"(r2), "=r"(r3) : "r"(addr))

#define MMA_F16(d, a0, a1, a2, a3, b0, b1)                                    \
    asm volatile(                                                             \
        "mma.sync.aligned.m16n8k16.row.col.f32.f16.f16.f32 "                  \
        "{%0,%1,%2,%3}, {%4,%5,%6,%7}, {%8,%9}, {%0,%1,%2,%3};"               \
        : "+f"((d)[0]), "+f"((d)[1]), "+f"((d)[2]), "+f"((d)[3])              \
        : "r"(a0), "r"(a1), "r"(a2), "r"(a3), "r"(b0), "r"(b1))

__device__ __forceinline__ uint32_t packh2(float a, float b) {
    __half2 h = __floats2half2_rn(a, b);
    return *(uint32_t*)&h;
}

// 64B-row swizzle (GEMM tiles: 32 halves/row)
__device__ __forceinline__ uint32_t swz(int r, int c) {
    return (uint32_t)(r * 64 + ((c ^ ((r >> 1) & 3)) << 4));
}
// 128B-row swizzle (attention tiles: 64 halves/row, 8 chunks)
__device__ __forceinline__ uint32_t swz128(int r, int c) {
    return (uint32_t)(r * 128 + ((c ^ (r & 7)) << 4));
}

// ---------------------------------------------------------------------------
// fp16 tensor-core GEMM: C slice = A[M,512] * B[N,512]^T
// CTA 128x256, BK=32, 256 thr; cp.async double buffer. out_half: fp16 C.
// remap: row m -> (m>>7)*512 + (m&127);  epi: +bias, post-mask zero (fp32 C).
// ---------------------------------------------------------------------------
#define ABUF_B 8192
#define BBUF_B 16384
#define BUF_B  (ABUF_B + BBUF_B)
#define GEMM_SMEM (2 * BUF_B)           // 49152

__global__ __launch_bounds__(256, 1) void gemm_h(
    const __half* __restrict__ A, const __half* __restrict__ B,
    float* __restrict__ C, int ldc, int col_off, int remap, int epi,
    int out_half,
    const float* __restrict__ bias, const unsigned char* __restrict__ post)
{
    extern __shared__ char smem[];
    const uint32_t sb = smem_u32(smem);
    const int tid  = threadIdx.x;
    const int lane = tid & 31;
    const int warp = tid >> 5;
    const int gid  = lane >> 2;
    const int tg   = lane & 3;
    const int wm   = warp >> 2;
    const int wn   = warp & 3;
    const int bm   = blockIdx.y * 128;
    const int bn   = blockIdx.x * 256;
    const int pr   = tid >> 2;
    const int pc   = tid & 3;

    float acc[4][8][4];
#pragma unroll
    for (int mi = 0; mi < 4; mi++)
#pragma unroll
        for (int ni = 0; ni < 8; ni++)
#pragma unroll
            for (int r = 0; r < 4; r++) acc[mi][ni][r] = 0.f;

    const int a_roff = (lane & 7) + ((lane >> 3) & 1) * 8;
    const int a_coff = lane >> 4;
    const int b_noff = (lane & 7) + (lane >> 4) * 8;
    const int b_coff = (lane >> 3) & 1;

#define ISSUE(kt, buf) do {                                                   \
        const uint32_t ab = sb + (buf) * BUF_B;                               \
        const uint32_t bb = ab + ABUF_B;                                      \
        _Pragma("unroll")                                                     \
        for (int s = 0; s < 2; s++) {                                         \
            int r = pr + s * 64;                                              \
            int ga = bm + r;                                                  \
            if (remap) ga = ((ga >> 7) << 9) | (ga & 127);                    \
            CP_ASYNC16(ab + swz(r, pc),                                       \
                       &A[(size_t)ga * 512 + (kt) * 32 + pc * 8]);            \
        }                                                                     \
        _Pragma("unroll")                                                     \
        for (int s = 0; s < 4; s++) {                                         \
            int r = pr + s * 64;                                              \
            CP_ASYNC16(bb + swz(r, pc),                                       \
                       &B[(size_t)(bn + r) * 512 + (kt) * 32 + pc * 8]);      \
        }                                                                     \
        CP_COMMIT();                                                          \
    } while (0)

    ISSUE(0, 0);

#pragma unroll 1
    for (int kt = 0; kt < 16; kt++) {
        const int buf = kt & 1;
        if (kt < 15) { ISSUE(kt + 1, buf ^ 1); CP_WAIT1(); }
        else         { CP_WAIT0(); }
        __syncthreads();

        const uint32_t ab = sb + buf * BUF_B;
        const uint32_t bb = ab + ABUF_B;
#pragma unroll
        for (int ks = 0; ks < 2; ks++) {
            uint32_t af[4][4], bf[4][4];
#pragma unroll
            for (int mi = 0; mi < 4; mi++)
                LDMATRIX_X4(af[mi][0], af[mi][1], af[mi][2], af[mi][3],
                            ab + swz(wm * 64 + mi * 16 + a_roff,
                                     2 * ks + a_coff));
#pragma unroll
            for (int ni2 = 0; ni2 < 4; ni2++)
                LDMATRIX_X4(bf[ni2][0], bf[ni2][1], bf[ni2][2], bf[ni2][3],
                            bb + swz(wn * 64 + ni2 * 16 + b_noff,
                                     2 * ks + b_coff));
#pragma unroll
            for (int mi = 0; mi < 4; mi++)
#pragma unroll
                for (int ni2 = 0; ni2 < 4; ni2++) {
                    MMA_F16(acc[mi][2 * ni2],
                            af[mi][0], af[mi][1], af[mi][2], af[mi][3],
                            bf[ni2][0], bf[ni2][1]);
                    MMA_F16(acc[mi][2 * ni2 + 1],
                            af[mi][0], af[mi][1], af[mi][2], af[mi][3],
                            bf[ni2][2], bf[ni2][3]);
                }
        }
        __syncthreads();
    }
#undef ISSUE

    const int i32 = g_mask_i32;
#pragma unroll
    for (int mi = 0; mi < 4; mi++) {
        int rbase = bm + wm * 64 + mi * 16 + gid;
#pragma unroll
        for (int hf = 0; hf < 2; hf++) {
            int row  = rbase + hf * 8;
            int grow = remap ? (((row >> 7) << 9) | (row & 127)) : row;
            float keep = 1.f;
            if (epi) keep = (mask_at(post, grow, i32) == 0) ? 1.f : 0.f;
#pragma unroll
            for (int ni = 0; ni < 8; ni++) {
                int col = bn + wn * 64 + ni * 8 + 2 * tg;
                float v0 = acc[mi][ni][hf * 2 + 0];
                float v1 = acc[mi][ni][hf * 2 + 1];
                if (epi) {
                    v0 = (v0 + bias[col])     * keep;
                    v1 = (v1 + bias[col + 1]) * keep;
                }
                if (out_half) {
                    __half* ch = (__half*)C;
                    __half2 hv = __floats2half2_rn(v0, v1);
                    *(__half2*)&ch[(size_t)grow * ldc + col_off + col] = hv;
                } else {
                    *(float2*)&C[(size_t)grow * ldc + col_off + col] =
                        make_float2(v0, v1);
                }
            }
        }
    }
}

// ---------------------------------------------------------------------------
// Fused flash-style attention on tensor cores. CTA = (b, h), 128 thr (4 warps).
// Each warp owns 32 query rows (2 m16 tiles). Entities in 64-wide tiles,
// double-buffered cp.async. QK^T and P*V via mma.m16n8k16; P fragments are
// repacked QK accumulators (no smem round-trip). Masks LDG'd (no reuse).
// w_i = e_i*d_i / (T + 1e-8*S),  e_i = valid_i * exp(l_i / 8)
// ---------------------------------------------------------------------------
__global__ __launch_bounds__(128, 2) void attn_mma(
    const __half* __restrict__ qkvh,
    const unsigned char* __restrict__ pre,
    const float* __restrict__ diff,
    __half* __restrict__ attn_h)
{
    __shared__ __align__(128) char q_sm[16384];
    __shared__ __align__(128) char k_sm[2][8192];
    __shared__ __align__(128) char v_sm[2][8192];

    const int b    = blockIdx.x;
    const int h    = blockIdx.y;
    const int tid  = threadIdx.x;
    const int lane = tid & 31;
    const int warp = tid >> 5;
    const int gid  = lane >> 2;
    const int tg   = lane & 3;
    const int i32  = g_mask_i32;

    const uint32_t qsb = smem_u32(q_sm);
    const uint32_t ksb = smem_u32(k_sm);
    const uint32_t vsb = smem_u32(v_sm);

    const __half* qptr = qkvh + (size_t)b * 512 * F3_ + h * HD_;
    const __half* kptr = qptr + EMB_;
    const __half* vptr = qptr + 2 * EMB_;

    // ldmatrix address components (same derivation as gemm_h, validated R6)
    const int a_roff = (lane & 7) + ((lane >> 3) & 1) * 8;
    const int a_coff = lane >> 4;
    const int b_noff = (lane & 7) + (lane >> 4) * 8;
    const int b_coff = (lane >> 3) & 1;
    // V trans-ldmatrix lane address: row = ent, chunk = hd group
    const int v_roff = lane & 15;
    const int v_coff = lane >> 4;

#define AT_ISSUE_KV(kt, buf) do {                                             \
        const uint32_t kb_ = ksb + (buf) * 8192;                              \
        const uint32_t vb_ = vsb + (buf) * 8192;                              \
        _Pragma("unroll")                                                     \
        for (int s = 0; s < 4; s++) {                                         \
            int r = (tid >> 3) + s * 16;                                      \
            int c = tid & 7;                                                  \
            size_t go = (size_t)((kt) * 64 + r) * F3_ + c * 8;                \
            CP_ASYNC16(kb_ + swz128(r, c), kptr + go);                        \
            CP_ASYNC16(vb_ + swz128(r, c), vptr + go);                        \
        }                                                                     \
        CP_COMMIT();                                                          \
    } while (0)

    // prologue: Q (+first KV tile) then second KV tile
#pragma unroll
    for (int s = 0; s < 8; s++) {
        int r = (tid >> 3) + s * 16;
        int c = tid & 7;
        CP_ASYNC16(qsb + swz128(r, c), qptr + (size_t)r * F3_ + c * 8);
    }
    AT_ISSUE_KV(0, 0);      // commits Q + KV0 as one group
    AT_ISSUE_KV(1, 1);
    CP_WAIT1();
    __syncthreads();

    // Q fragments (hoisted; constant across ktiles)
    uint32_t qa[2][4][4];
#pragma unroll
    for (int m = 0; m < 2; m++)
#pragma unroll
        for (int ks = 0; ks < 4; ks++)
            LDMATRIX_X4(qa[m][ks][0], qa[m][ks][1], qa[m][ks][2], qa[m][ks][3],
                        qsb + swz128(warp * 32 + m * 16 + a_roff,
                                     2 * ks + a_coff));

    float oacc[2][8][4];
#pragma unroll
    for (int m = 0; m < 2; m++)
#pragma unroll
        for (int n = 0; n < 8; n++)
#pragma unroll
            for (int r = 0; r < 4; r++) oacc[m][n][r] = 0.f;
    float Ssum[2][2] = {{0.f, 0.f}, {0.f, 0.f}};
    float Tsum[2][2] = {{0.f, 0.f}, {0.f, 0.f}};

#pragma unroll 1
    for (int kt = 0; kt < 8; kt++) {
        const int buf = kt & 1;
        const uint32_t kb = ksb + buf * 8192;
        const uint32_t vb = vsb + buf * 8192;

        // ---- QK^T ----
        float lacc[2][8][4];
#pragma unroll
        for (int m = 0; m < 2; m++)
#pragma unroll
            for (int j = 0; j < 8; j++)
#pragma unroll
                for (int r = 0; r < 4; r++) lacc[m][j][r] = 0.f;

#pragma unroll
        for (int ks = 0; ks < 4; ks++) {
            uint32_t kf[4][4];
#pragma unroll
            for (int g = 0; g < 4; g++)
                LDMATRIX_X4(kf[g][0], kf[g][1], kf[g][2], kf[g][3],
                            kb + swz128(g * 16 + b_noff, 2 * ks + b_coff));
#pragma unroll
            for (int m = 0; m < 2; m++)
#pragma unroll
                for (int g = 0; g < 4; g++) {
                    MMA_F16(lacc[m][2 * g],
                            qa[m][ks][0], qa[m][ks][1], qa[m][ks][2], qa[m][ks][3],
                            kf[g][0], kf[g][1]);
                    MMA_F16(lacc[m][2 * g + 1],
                            qa[m][ks][0], qa[m][ks][1], qa[m][ks][2], qa[m][ks][3],
                            kf[g][2], kf[g][3]);
                }
        }

        // ---- masks + exp; lacc becomes ed ----
#pragma unroll
        for (int m = 0; m < 2; m++) {
            const int q0 = warp * 32 + m * 16 + gid;
#pragma unroll
            for (int j = 0; j < 8; j++) {
                const int ent = kt * 64 + j * 8 + tg * 2;
                const int i0  = (b * NQ_ + q0) * NE_ + ent;
                const int i1  = i0 + 8 * NE_;
                float2 d0 = *(const float2*)&diff[i0];
                float2 d1 = *(const float2*)&diff[i1];
                float va0, va1, vb0, vb1;
                valid2(pre, i0, i32, va0, va1);
                valid2(pre, i1, i32, vb0, vb1);
                float e0 = __expf(lacc[m][j][0] * 0.125f) * va0;
                float e1 = __expf(lacc[m][j][1] * 0.125f) * va1;
                float e2 = __expf(lacc[m][j][2] * 0.125f) * vb0;
                float e3 = __expf(lacc[m][j][3] * 0.125f) * vb1;
                float ed0 = e0 * d0.x, ed1 = e1 * d0.y;
                float ed2 = e2 * d1.x, ed3 = e3 * d1.y;
                Ssum[m][0] += e0 + e1;   Tsum[m][0] += ed0 + ed1;
                Ssum[m][1] += e2 + e3;   Tsum[m][1] += ed2 + ed3;
                lacc[m][j][0] = ed0; lacc[m][j][1] = ed1;
                lacc[m][j][2] = ed2; lacc[m][j][3] = ed3;
            }
        }

        // ---- P * V ----
#pragma unroll
        for (int ks = 0; ks < 4; ks++) {
            uint32_t pa[2][4];
#pragma unroll
            for (int m = 0; m < 2; m++) {
                pa[m][0] = packh2(lacc[m][2 * ks][0],     lacc[m][2 * ks][1]);
                pa[m][1] = packh2(lacc[m][2 * ks][2],     lacc[m][2 * ks][3]);
                pa[m][2] = packh2(lacc[m][2 * ks + 1][0], lacc[m][2 * ks + 1][1]);
                pa[m][3] = packh2(lacc[m][2 * ks + 1][2], lacc[m][2 * ks + 1][3]);
            }
#pragma unroll
            for (int ng = 0; ng < 4; ng++) {
                uint32_t vf0, vf1, vf2, vf3;
                LDMATRIX_X4_T(vf0, vf1, vf2, vf3,
                              vb + swz128(ks * 16 + v_roff, 2 * ng + v_coff));
#pragma unroll
                for (int m = 0; m < 2; m++) {
                    MMA_F16(oacc[m][2 * ng],
                            pa[m][0], pa[m][1], pa[m][2], pa[m][3], vf0, vf1);
                    MMA_F16(oacc[m][2 * ng + 1],
                            pa[m][0], pa[m][1], pa[m][2], pa[m][3], vf2, vf3);
                }
            }
        }

        __syncthreads();
        if (kt == 7) break;
        if (kt + 2 < 8) { AT_ISSUE_KV(kt + 2, buf); CP_WAIT1(); }
        else            { CP_WAIT0(); }
        __syncthreads();
    }
#undef AT_ISSUE_KV

    // ---- row reductions + output ----
#pragma unroll
    for (int m = 0; m < 2; m++)
#pragma unroll
        for (int hf = 0; hf < 2; hf++) {
            float s = Ssum[m][hf], t = Tsum[m][hf];
            s += __shfl_xor_sync(0xFFFFFFFFu, s, 1);
            s += __shfl_xor_sync(0xFFFFFFFFu, s, 2);
            t += __shfl_xor_sync(0xFFFFFFFFu, t, 1);
            t += __shfl_xor_sync(0xFFFFFFFFu, t, 2);
            float inv = (s > 0.f) ? (1.f / (t + 1e-8f * s)) : 0.f;
            const int q = warp * 32 + m * 16 + gid + hf * 8;
            __half* orow = &attn_h[((size_t)b * NQ_ + q) * EMB_ + h * HD_];
#pragma unroll
            for (int n = 0; n < 8; n++) {
                __half2 hv = __floats2half2_rn(oacc[m][n][hf * 2 + 0] * inv,
                                               oacc[m][n][hf * 2 + 1] * inv);
                *(__half2*)&orow[n * 8 + tg * 2] = hv;
            }
        }
}

// ---------------------------------------------------------------------------
// Launch
// ---------------------------------------------------------------------------
extern "C" void kernel_launch(void* const* d_in, const int* in_sizes, int n_in,
                              void* d_out, int out_size) {
    const float* entities     = (const float*)d_in[0];
    const unsigned char* pre  = (const unsigned char*)d_in[1];
    const float* diff         = (const float*)d_in[2];
    const unsigned char* post = (const unsigned char*)d_in[3];
    const float* W_in         = (const float*)d_in[4];
    const float* W_out        = (const float*)d_in[5];
    const float* b_out        = (const float*)d_in[6];
    float* out                = (float*)d_out;

    __half* qkvh   = nullptr;
    __half* ent_h  = nullptr;
    __half* win_h  = nullptr;
    __half* wout_h = nullptr;
    __half* attn_h = nullptr;
    cudaGetSymbolAddress((void**)&qkvh,   g_qkv_h);
    cudaGetSymbolAddress((void**)&ent_h,  g_ent_h);
    cudaGetSymbolAddress((void**)&win_h,  g_win_h);
    cudaGetSymbolAddress((void**)&wout_h, g_wout_h);
    cudaGetSymbolAddress((void**)&attn_h, g_attn_h);

    cudaFuncSetAttribute(gemm_h, cudaFuncAttributeMaxDynamicSharedMemorySize,
                         GEMM_SMEM);

    detect_mask_kernel<<<1, 32>>>(pre);

    // fp32 -> fp16 input conversions
    cvt_f2h<<<8192, 256>>>((const float4*)entities, (uint2*)ent_h,
                           (BS_ * NE_ * 512) / 4);
    cvt_f2h<<<1024, 256>>>((const float4*)W_in, (uint2*)win_h,
                           (F3_ * 512) / 4);
    cvt_f2h<<<512, 256>>>((const float4*)W_out, (uint2*)wout_h,
                          (EMB_ * EMB_) / 4);

    // KV: qkv[:, 512:1536] = entities @ W_in[512:,:]^T (fp16 out)
    gemm_h<<<dim3(4, 512), 256, GEMM_SMEM>>>(
        ent_h, win_h + 512 * 512, (float*)qkvh, F3_, 512, 0, 0, 1,
        nullptr, nullptr);

    // Q: first 128 rows per batch (remapped, fp16 out)
    gemm_h<<<dim3(2, 128), 256, GEMM_SMEM>>>(
        ent_h, win_h, (float*)qkvh, F3_, 0, 1, 0, 1, nullptr, nullptr);

    // fused tensor-core attention -> half output
    attn_mma<<<dim3(BS_, H_), 128>>>(qkvh, pre, diff, attn_h);

    // out = attn @ W_out^T + b_out, post-masked (fp32 out)
    gemm_h<<<dim3(2, 128), 256, GEMM_SMEM>>>(
        attn_h, wout_h, out, EMB_, 0, 0, 1, 0, b_out, post);
}

// round 9
// speedup vs baseline: 7.5345x; 1.2016x over previous
#include <cuda_runtime.h>
#include <cuda_fp16.h>
#include <cstdint>

// Problem constants
#define BS_  128
#define NE_  512
#define NQ_  128
#define EMB_ 512
#define H_   8
#define HD_  64
#define F3_  1536

// Scratch (allocation-free rule: __device__ globals)
__device__ __half g_qkv_h[(size_t)BS_ * NE_ * F3_];      // fp16 qkv
__device__ __half g_ent_h[(size_t)BS_ * NE_ * 512];      // half entities
__device__ __half g_win_h[(size_t)F3_ * 512];            // half W_in
__device__ __half g_wout_h[(size_t)EMB_ * EMB_];         // half W_out
__device__ __half g_attn_h[(size_t)BS_ * NQ_ * EMB_];    // half attention output
__device__ float  g_vd[(size_t)BS_ * NQ_ * NE_];         // valid? diff : -1
__device__ int    g_mask_i32;

// ---------------------------------------------------------------------------
// Mask dtype detection (jax bool may arrive as int32 or uint8)
// ---------------------------------------------------------------------------
__global__ void detect_mask_kernel(const unsigned char* __restrict__ p) {
    if (threadIdx.x == 0) {
        int i32 = 1;
        for (int g = 0; g < 256; g++) {
            if (p[4 * g + 1] | p[4 * g + 2] | p[4 * g + 3]) { i32 = 0; break; }
        }
        g_mask_i32 = i32;
    }
}
__device__ __forceinline__ int mask_at(const unsigned char* __restrict__ p,
                                       int idx, int i32) {
    return (int)p[i32 ? (idx << 2) : idx];
}
__device__ __forceinline__ void valid2(const unsigned char* __restrict__ p,
                                       int idx, int i32, float& v0, float& v1) {
    if (i32) {
        int2 q = *(const int2*)(p + ((size_t)idx << 2));
        v0 = q.x ? 0.f : 1.f;
        v1 = q.y ? 0.f : 1.f;
    } else {
        unsigned short s = *(const unsigned short*)(p + idx);
        v0 = (s & 0xFF) ? 0.f : 1.f;
        v1 = (s >> 8)   ? 0.f : 1.f;
    }
}

// ---------------------------------------------------------------------------
// Fold pre_mask into diff_mask: vd = valid ? diff : -1.0  (exact fp32)
// ---------------------------------------------------------------------------
__global__ void pack_vd(const unsigned char* __restrict__ pre,
                        const float* __restrict__ diff,
                        float* __restrict__ vd, int n2) {
    const int i32 = g_mask_i32;
    for (int i = blockIdx.x * blockDim.x + threadIdx.x; i < n2;
         i += gridDim.x * blockDim.x) {
        float2 d = ((const float2*)diff)[i];
        float v0, v1;
        valid2(pre, 2 * i, i32, v0, v1);
        float2 o;
        o.x = (v0 > 0.f) ? d.x : -1.f;
        o.y = (v1 > 0.f) ? d.y : -1.f;
        ((float2*)vd)[i] = o;
    }
}

// ---------------------------------------------------------------------------
// fp32 -> fp16 bulk convert
// ---------------------------------------------------------------------------
__global__ void cvt_f2h(const float4* __restrict__ src, uint2* __restrict__ dst,
                        int n4) {
    for (int i = blockIdx.x * blockDim.x + threadIdx.x; i < n4;
         i += gridDim.x * blockDim.x) {
        float4 v = src[i];
        __half2 a = __floats2half2_rn(v.x, v.y);
        __half2 b = __floats2half2_rn(v.z, v.w);
        uint2 o;
        o.x = *(uint32_t*)&a;
        o.y = *(uint32_t*)&b;
        dst[i] = o;
    }
}

// ---------------------------------------------------------------------------
// PTX helpers
// ---------------------------------------------------------------------------
__device__ __forceinline__ uint32_t smem_u32(const void* p) {
    uint32_t a;
    asm("{ .reg .u64 t; cvta.to.shared.u64 t, %1; cvt.u32.u64 %0, t; }"
        : "=r"(a) : "l"(p));
    return a;
}
#define CP_ASYNC16(dst, src) \
    asm volatile("cp.async.cg.shared.global [%0], [%1], 16;" \
                 :: "r"(dst), "l"(src) : "memory")
#define CP_COMMIT() asm volatile("cp.async.commit_group;" ::: "memory")
#define CP_WAIT0()  asm volatile("cp.async.wait_group 0;" ::: "memory")
#define CP_WAIT1()  asm volatile("cp.async.wait_group 1;" ::: "memory")

#define LDMATRIX_X4(r0, r1, r2, r3, addr) \
    asm volatile("ldmatrix.sync.aligned.m8n8.x4.shared.b16 {%0,%1,%2,%3}, [%4];" \
                 : "=r"(r0), "=r"(r1), "=r"(r2), "=r"(r3) : "r"(addr))
#define LDMATRIX_X4_T(r0, r1, r2, r3, addr) \
    asm volatile("ldmatrix.sync.aligned.m8n8.x4.trans.shared.b16 {%0,%1,%2,%3}, [%4];" \
                 : "=r"(r0), "=r"(r1), "=r"(r2), "=r"(r3) : "r"(addr))

#define MMA_F16(d, a0, a1, a2, a3, b0, b1)                                    \
    asm volatile(                                                             \
        "mma.sync.aligned.m16n8k16.row.col.f32.f16.f16.f32 "                  \
        "{%0,%1,%2,%3}, {%4,%5,%6,%7}, {%8,%9}, {%0,%1,%2,%3};"               \
        : "+f"((d)[0]), "+f"((d)[1]), "+f"((d)[2]), "+f"((d)[3])              \
        : "r"(a0), "r"(a1), "r"(a2), "r"(a3), "r"(b0), "r"(b1))

__device__ __forceinline__ uint32_t packh2(float a, float b) {
    __half2 h = __floats2half2_rn(a, b);
    return *(uint32_t*)&h;
}

// 64B-row swizzle (GEMM tiles: 32 halves/row)
__device__ __forceinline__ uint32_t swz(int r, int c) {
    return (uint32_t)(r * 64 + ((c ^ ((r >> 1) & 3)) << 4));
}
// 128B-row swizzle (attention tiles: 64 halves/row, 8 chunks)
__device__ __forceinline__ uint32_t swz128(int r, int c) {
    return (uint32_t)(r * 128 + ((c ^ (r & 7)) << 4));
}

// ---------------------------------------------------------------------------
// fp16 tensor-core GEMM: C slice = A[M,512] * B[N,512]^T
// CTA 128x256, BK=32, 256 thr; 3-stage cp.async pipeline, ONE bar per k-iter.
// remap: row m -> (m>>7)*512 + (m&127);  epi: +bias, post-mask zero (fp32 C).
// oscale: multiplied into outputs (used to pre-scale Q by 1/8, exact in fp16).
// ---------------------------------------------------------------------------
#define ABUF_B 8192
#define BBUF_B 16384
#define BUF_B  (ABUF_B + BBUF_B)
#define GEMM_SMEM (3 * BUF_B)           // 73728

__global__ __launch_bounds__(256, 1) void gemm_h(
    const __half* __restrict__ A, const __half* __restrict__ B,
    float* __restrict__ C, int ldc, int col_off, int remap, int epi,
    int out_half, float oscale,
    const float* __restrict__ bias, const unsigned char* __restrict__ post)
{
    extern __shared__ char smem[];
    const uint32_t sb = smem_u32(smem);
    const int tid  = threadIdx.x;
    const int lane = tid & 31;
    const int warp = tid >> 5;
    const int gid  = lane >> 2;
    const int tg   = lane & 3;
    const int wm   = warp >> 2;
    const int wn   = warp & 3;
    const int bm   = blockIdx.y * 128;
    const int bn   = blockIdx.x * 256;
    const int pr   = tid >> 2;
    const int pc   = tid & 3;

    float acc[4][8][4];
#pragma unroll
    for (int mi = 0; mi < 4; mi++)
#pragma unroll
        for (int ni = 0; ni < 8; ni++)
#pragma unroll
            for (int r = 0; r < 4; r++) acc[mi][ni][r] = 0.f;

    const int a_roff = (lane & 7) + ((lane >> 3) & 1) * 8;
    const int a_coff = lane >> 4;
    const int b_noff = (lane & 7) + (lane >> 4) * 8;
    const int b_coff = (lane >> 3) & 1;

#define ISSUE(kt, buf) do {                                                   \
        const uint32_t ab_ = sb + (buf) * BUF_B;                              \
        const uint32_t bb_ = ab_ + ABUF_B;                                    \
        _Pragma("unroll")                                                     \
        for (int s = 0; s < 2; s++) {                                         \
            int r = pr + s * 64;                                              \
            int ga = bm + r;                                                  \
            if (remap) ga = ((ga >> 7) << 9) | (ga & 127);                    \
            CP_ASYNC16(ab_ + swz(r, pc),                                      \
                       &A[(size_t)ga * 512 + (kt) * 32 + pc * 8]);            \
        }                                                                     \
        _Pragma("unroll")                                                     \
        for (int s = 0; s < 4; s++) {                                         \
            int r = pr + s * 64;                                              \
            CP_ASYNC16(bb_ + swz(r, pc),                                      \
                       &B[(size_t)(bn + r) * 512 + (kt) * 32 + pc * 8]);      \
        }                                                                     \
        CP_COMMIT();                                                          \
    } while (0)

    ISSUE(0, 0);
    ISSUE(1, 1);
    CP_WAIT1();
    __syncthreads();

#pragma unroll 1
    for (int kt = 0; kt < 16; kt++) {
        const uint32_t ab = sb + (kt % 3) * BUF_B;
        const uint32_t bb = ab + ABUF_B;
#pragma unroll
        for (int ks = 0; ks < 2; ks++) {
            uint32_t af[4][4], bf[4][4];
#pragma unroll
            for (int mi = 0; mi < 4; mi++)
                LDMATRIX_X4(af[mi][0], af[mi][1], af[mi][2], af[mi][3],
                            ab + swz(wm * 64 + mi * 16 + a_roff,
                                     2 * ks + a_coff));
#pragma unroll
            for (int ni2 = 0; ni2 < 4; ni2++)
                LDMATRIX_X4(bf[ni2][0], bf[ni2][1], bf[ni2][2], bf[ni2][3],
                            bb + swz(wn * 64 + ni2 * 16 + b_noff,
                                     2 * ks + b_coff));
#pragma unroll
            for (int mi = 0; mi < 4; mi++)
#pragma unroll
                for (int ni2 = 0; ni2 < 4; ni2++) {
                    MMA_F16(acc[mi][2 * ni2],
                            af[mi][0], af[mi][1], af[mi][2], af[mi][3],
                            bf[ni2][0], bf[ni2][1]);
                    MMA_F16(acc[mi][2 * ni2 + 1],
                            af[mi][0], af[mi][1], af[mi][2], af[mi][3],
                            bf[ni2][2], bf[ni2][3]);
                }
        }
        if (kt < 15) {
            if (kt + 2 < 16) { ISSUE(kt + 2, (kt + 2) % 3); CP_WAIT1(); }
            else             { CP_WAIT0(); }
            __syncthreads();
        }
    }
#undef ISSUE

    const int i32 = g_mask_i32;
#pragma unroll
    for (int mi = 0; mi < 4; mi++) {
        int rbase = bm + wm * 64 + mi * 16 + gid;
#pragma unroll
        for (int hf = 0; hf < 2; hf++) {
            int row  = rbase + hf * 8;
            int grow = remap ? (((row >> 7) << 9) | (row & 127)) : row;
            float keep = 1.f;
            if (epi) keep = (mask_at(post, grow, i32) == 0) ? 1.f : 0.f;
#pragma unroll
            for (int ni = 0; ni < 8; ni++) {
                int col = bn + wn * 64 + ni * 8 + 2 * tg;
                float v0 = acc[mi][ni][hf * 2 + 0] * oscale;
                float v1 = acc[mi][ni][hf * 2 + 1] * oscale;
                if (epi) {
                    v0 = (v0 + bias[col])     * keep;
                    v1 = (v1 + bias[col + 1]) * keep;
                }
                if (out_half) {
                    __half* ch = (__half*)C;
                    __half2 hv = __floats2half2_rn(v0, v1);
                    *(__half2*)&ch[(size_t)grow * ldc + col_off + col] = hv;
                } else {
                    *(float2*)&C[(size_t)grow * ldc + col_off + col] =
                        make_float2(v0, v1);
                }
            }
        }
    }
}

// ---------------------------------------------------------------------------
// Fused flash-style attention on tensor cores. CTA = (b, h), 128 thr (4 warps).
// Q pre-scaled by 1/8 -> e = exp(l). Masks pre-folded: vd = valid? diff : -1.
// 3-stage KV pipeline, one bar per tile. P fragments repacked from QK accum.
// w_i = e_i*d_i / (T + 1e-8*S)
// ---------------------------------------------------------------------------
#define ATT_SMEM (16384 + 3 * 8192 + 3 * 8192)   // 65536

__global__ __launch_bounds__(128, 2) void attn_mma(
    const __half* __restrict__ qkvh,
    const float* __restrict__ vd,
    __half* __restrict__ attn_h)
{
    extern __shared__ char dynsm[];
    const uint32_t qsb = smem_u32(dynsm);
    const uint32_t ksb = qsb + 16384;
    const uint32_t vsb = qsb + 16384 + 3 * 8192;

    const int b    = blockIdx.x;
    const int h    = blockIdx.y;
    const int tid  = threadIdx.x;
    const int lane = tid & 31;
    const int warp = tid >> 5;
    const int gid  = lane >> 2;
    const int tg   = lane & 3;

    const __half* qptr = qkvh + (size_t)b * 512 * F3_ + h * HD_;
    const __half* kptr = qptr + EMB_;
    const __half* vptr = qptr + 2 * EMB_;

    const int a_roff = (lane & 7) + ((lane >> 3) & 1) * 8;
    const int a_coff = lane >> 4;
    const int b_noff = (lane & 7) + (lane >> 4) * 8;
    const int b_coff = (lane >> 3) & 1;
    const int v_roff = lane & 15;
    const int v_coff = lane >> 4;

#define AT_ISSUE_KV(kt, buf) do {                                             \
        const uint32_t kb_ = ksb + (buf) * 8192;                              \
        const uint32_t vb_ = vsb + (buf) * 8192;                              \
        _Pragma("unroll")                                                     \
        for (int s = 0; s < 4; s++) {                                         \
            int r = (tid >> 3) + s * 16;                                      \
            int c = tid & 7;                                                  \
            size_t go = (size_t)((kt) * 64 + r) * F3_ + c * 8;                \
            CP_ASYNC16(kb_ + swz128(r, c), kptr + go);                        \
            CP_ASYNC16(vb_ + swz128(r, c), vptr + go);                        \
        }                                                                     \
        CP_COMMIT();                                                          \
    } while (0)

    // prologue: Q + KV0 (group 0), KV1 (group 1)
#pragma unroll
    for (int s = 0; s < 8; s++) {
        int r = (tid >> 3) + s * 16;
        int c = tid & 7;
        CP_ASYNC16(qsb + swz128(r, c), qptr + (size_t)r * F3_ + c * 8);
    }
    AT_ISSUE_KV(0, 0);
    AT_ISSUE_KV(1, 1);
    CP_WAIT1();
    __syncthreads();

    // Q fragments (constant across ktiles)
    uint32_t qa[2][4][4];
#pragma unroll
    for (int m = 0; m < 2; m++)
#pragma unroll
        for (int ks = 0; ks < 4; ks++)
            LDMATRIX_X4(qa[m][ks][0], qa[m][ks][1], qa[m][ks][2], qa[m][ks][3],
                        qsb + swz128(warp * 32 + m * 16 + a_roff,
                                     2 * ks + a_coff));

    float oacc[2][8][4];
#pragma unroll
    for (int m = 0; m < 2; m++)
#pragma unroll
        for (int n = 0; n < 8; n++)
#pragma unroll
            for (int r = 0; r < 4; r++) oacc[m][n][r] = 0.f;
    float Ssum[2][2] = {{0.f, 0.f}, {0.f, 0.f}};
    float Tsum[2][2] = {{0.f, 0.f}, {0.f, 0.f}};

    const float* vdrow0 = vd + ((size_t)(b * NQ_ + warp * 32 + gid)) * NE_;

#pragma unroll 1
    for (int kt = 0; kt < 8; kt++) {
        const int buf = kt % 3;
        const uint32_t kb = ksb + buf * 8192;
        const uint32_t vb = vsb + buf * 8192;

        // ---- QK^T ----
        float lacc[2][8][4];
#pragma unroll
        for (int m = 0; m < 2; m++)
#pragma unroll
            for (int j = 0; j < 8; j++)
#pragma unroll
                for (int r = 0; r < 4; r++) lacc[m][j][r] = 0.f;

#pragma unroll
        for (int ks = 0; ks < 4; ks++) {
            uint32_t kf[4][4];
#pragma unroll
            for (int g = 0; g < 4; g++)
                LDMATRIX_X4(kf[g][0], kf[g][1], kf[g][2], kf[g][3],
                            kb + swz128(g * 16 + b_noff, 2 * ks + b_coff));
#pragma unroll
            for (int m = 0; m < 2; m++)
#pragma unroll
                for (int g = 0; g < 4; g++) {
                    MMA_F16(lacc[m][2 * g],
                            qa[m][ks][0], qa[m][ks][1], qa[m][ks][2], qa[m][ks][3],
                            kf[g][0], kf[g][1]);
                    MMA_F16(lacc[m][2 * g + 1],
                            qa[m][ks][0], qa[m][ks][1], qa[m][ks][2], qa[m][ks][3],
                            kf[g][2], kf[g][3]);
                }
        }

        // ---- folded mask + exp; lacc becomes ed ----
#pragma unroll
        for (int m = 0; m < 2; m++) {
            const float* vdp = vdrow0 + (size_t)m * 16 * NE_ + kt * 64 + tg * 2;
#pragma unroll
            for (int j = 0; j < 8; j++) {
                float2 d0 = *(const float2*)(vdp + j * 8);
                float2 d1 = *(const float2*)(vdp + 8 * NE_ + j * 8);
                float x0 = __expf(lacc[m][j][0]);
                float x1 = __expf(lacc[m][j][1]);
                float x2 = __expf(lacc[m][j][2]);
                float x3 = __expf(lacc[m][j][3]);
                float e0 = (d0.x >= 0.f) ? x0 : 0.f;
                float e1 = (d0.y >= 0.f) ? x1 : 0.f;
                float e2 = (d1.x >= 0.f) ? x2 : 0.f;
                float e3 = (d1.y >= 0.f) ? x3 : 0.f;
                float ed0 = x0 * fmaxf(d0.x, 0.f);
                float ed1 = x1 * fmaxf(d0.y, 0.f);
                float ed2 = x2 * fmaxf(d1.x, 0.f);
                float ed3 = x3 * fmaxf(d1.y, 0.f);
                Ssum[m][0] += e0 + e1;   Tsum[m][0] += ed0 + ed1;
                Ssum[m][1] += e2 + e3;   Tsum[m][1] += ed2 + ed3;
                lacc[m][j][0] = ed0; lacc[m][j][1] = ed1;
                lacc[m][j][2] = ed2; lacc[m][j][3] = ed3;
            }
        }

        // ---- P * V ----
#pragma unroll
        for (int ks = 0; ks < 4; ks++) {
            uint32_t pa[2][4];
#pragma unroll
            for (int m = 0; m < 2; m++) {
                pa[m][0] = packh2(lacc[m][2 * ks][0],     lacc[m][2 * ks][1]);
                pa[m][1] = packh2(lacc[m][2 * ks][2],     lacc[m][2 * ks][3]);
                pa[m][2] = packh2(lacc[m][2 * ks + 1][0], lacc[m][2 * ks + 1][1]);
                pa[m][3] = packh2(lacc[m][2 * ks + 1][2], lacc[m][2 * ks + 1][3]);
            }
#pragma unroll
            for (int ng = 0; ng < 4; ng++) {
                uint32_t vf0, vf1, vf2, vf3;
                LDMATRIX_X4_T(vf0, vf1, vf2, vf3,
                              vb + swz128(ks * 16 + v_roff, 2 * ng + v_coff));
#pragma unroll
                for (int m = 0; m < 2; m++) {
                    MMA_F16(oacc[m][2 * ng],
                            pa[m][0], pa[m][1], pa[m][2], pa[m][3], vf0, vf1);
                    MMA_F16(oacc[m][2 * ng + 1],
                            pa[m][0], pa[m][1], pa[m][2], pa[m][3], vf2, vf3);
                }
            }
        }

        if (kt < 7) {
            if (kt + 2 < 8) { AT_ISSUE_KV(kt + 2, (kt + 2) % 3); CP_WAIT1(); }
            else            { CP_WAIT0(); }
            __syncthreads();
        }
    }
#undef AT_ISSUE_KV

    // ---- row reductions + output ----
#pragma unroll
    for (int m = 0; m < 2; m++)
#pragma unroll
        for (int hf = 0; hf < 2; hf++) {
            float s = Ssum[m][hf], t = Tsum[m][hf];
            s += __shfl_xor_sync(0xFFFFFFFFu, s, 1);
            s += __shfl_xor_sync(0xFFFFFFFFu, s, 2);
            t += __shfl_xor_sync(0xFFFFFFFFu, t, 1);
            t += __shfl_xor_sync(0xFFFFFFFFu, t, 2);
            float inv = (s > 0.f) ? (1.f / (t + 1e-8f * s)) : 0.f;
            const int q = warp * 32 + m * 16 + gid + hf * 8;
            __half* orow = &attn_h[((size_t)b * NQ_ + q) * EMB_ + h * HD_];
#pragma unroll
            for (int n = 0; n < 8; n++) {
                __half2 hv = __floats2half2_rn(oacc[m][n][hf * 2 + 0] * inv,
                                               oacc[m][n][hf * 2 + 1] * inv);
                *(__half2*)&orow[n * 8 + tg * 2] = hv;
            }
        }
}

// ---------------------------------------------------------------------------
// Launch
// ---------------------------------------------------------------------------
extern "C" void kernel_launch(void* const* d_in, const int* in_sizes, int n_in,
                              void* d_out, int out_size) {
    const float* entities     = (const float*)d_in[0];
    const unsigned char* pre  = (const unsigned char*)d_in[1];
    const float* diff         = (const float*)d_in[2];
    const unsigned char* post = (const unsigned char*)d_in[3];
    const float* W_in         = (const float*)d_in[4];
    const float* W_out        = (const float*)d_in[5];
    const float* b_out        = (const float*)d_in[6];
    float* out                = (float*)d_out;

    __half* qkvh   = nullptr;
    __half* ent_h  = nullptr;
    __half* win_h  = nullptr;
    __half* wout_h = nullptr;
    __half* attn_h = nullptr;
    float*  vd     = nullptr;
    cudaGetSymbolAddress((void**)&qkvh,   g_qkv_h);
    cudaGetSymbolAddress((void**)&ent_h,  g_ent_h);
    cudaGetSymbolAddress((void**)&win_h,  g_win_h);
    cudaGetSymbolAddress((void**)&wout_h, g_wout_h);
    cudaGetSymbolAddress((void**)&attn_h, g_attn_h);
    cudaGetSymbolAddress((void**)&vd,     g_vd);

    cudaFuncSetAttribute(gemm_h, cudaFuncAttributeMaxDynamicSharedMemorySize,
                         GEMM_SMEM);
    cudaFuncSetAttribute(attn_mma, cudaFuncAttributeMaxDynamicSharedMemorySize,
                         ATT_SMEM);

    detect_mask_kernel<<<1, 32>>>(pre);

    // fp32 -> fp16 input conversions + mask folding
    cvt_f2h<<<8192, 256>>>((const float4*)entities, (uint2*)ent_h,
                           (BS_ * NE_ * 512) / 4);
    cvt_f2h<<<1024, 256>>>((const float4*)W_in, (uint2*)win_h,
                           (F3_ * 512) / 4);
    cvt_f2h<<<512, 256>>>((const float4*)W_out, (uint2*)wout_h,
                          (EMB_ * EMB_) / 4);
    pack_vd<<<4096, 256>>>(pre, diff, vd, (BS_ * NQ_ * NE_) / 2);

    // KV: qkv[:, 512:1536] = entities @ W_in[512:,:]^T (fp16 out)
    gemm_h<<<dim3(4, 512), 256, GEMM_SMEM>>>(
        ent_h, win_h + 512 * 512, (float*)qkvh, F3_, 512, 0, 0, 1, 1.0f,
        nullptr, nullptr);

    // Q: first 128 rows per batch (remapped, fp16 out, pre-scaled by 1/8)
    gemm_h<<<dim3(2, 128), 256, GEMM_SMEM>>>(
        ent_h, win_h, (float*)qkvh, F3_, 0, 1, 0, 1, 0.125f,
        nullptr, nullptr);

    // fused tensor-core attention -> half output
    attn_mma<<<dim3(BS_, H_), 128, ATT_SMEM>>>(qkvh, vd, attn_h);

    // out = attn @ W_out^T + b_out, post-masked (fp32 out)
    gemm_h<<<dim3(2, 128), 256, GEMM_SMEM>>>(
        attn_h, wout_h, out, EMB_, 0, 0, 1, 0, 1.0f, b_out, post);
}

// round 11
// speedup vs baseline: 8.8218x; 1.1708x over previous
#include <cuda_runtime.h>
#include <cuda_fp16.h>
#include <cstdint>

// Problem constants
#define BS_  128
#define NE_  512
#define NQ_  128
#define EMB_ 512
#define H_   8
#define HD_  64
#define F3_  1536

// Scratch (allocation-free rule: __device__ globals)
__device__ __half g_qkv_h[(size_t)BS_ * NE_ * F3_];      // fp16 qkv
__device__ __half g_ent_h[(size_t)BS_ * NE_ * 512];      // half entities
__device__ __half g_win_h[(size_t)F3_ * 512];            // half W_in
__device__ __half g_wout_h[(size_t)EMB_ * EMB_];         // half W_out
__device__ __half g_attn_h[(size_t)BS_ * NQ_ * EMB_];    // half attention output
__device__ float  g_vd[(size_t)BS_ * NQ_ * NE_];         // valid? diff : -1
__device__ int    g_mask_i32;

// ---------------------------------------------------------------------------
// Mask dtype detection (jax bool may arrive as int32 or uint8) — warp-parallel
// ---------------------------------------------------------------------------
__global__ void detect_mask_kernel(const unsigned char* __restrict__ p) {
    int t = threadIdx.x;
    unsigned acc = 0;
    for (int g = t; g < 256; g += 32)
        acc |= (unsigned)p[4 * g + 1] | p[4 * g + 2] | p[4 * g + 3];
    unsigned any = __ballot_sync(0xFFFFFFFFu, acc != 0);
    if (t == 0) g_mask_i32 = (any == 0) ? 1 : 0;
}
__device__ __forceinline__ int mask_at(const unsigned char* __restrict__ p,
                                       int idx, int i32) {
    return (int)p[i32 ? (idx << 2) : idx];
}
__device__ __forceinline__ void valid2(const unsigned char* __restrict__ p,
                                       int idx, int i32, float& v0, float& v1) {
    if (i32) {
        int2 q = *(const int2*)(p + ((size_t)idx << 2));
        v0 = q.x ? 0.f : 1.f;
        v1 = q.y ? 0.f : 1.f;
    } else {
        unsigned short s = *(const unsigned short*)(p + idx);
        v0 = (s & 0xFF) ? 0.f : 1.f;
        v1 = (s >> 8)   ? 0.f : 1.f;
    }
}

// ---------------------------------------------------------------------------
// Fold pre_mask into diff_mask: vd = valid ? diff : -1.0  (exact fp32)
// ---------------------------------------------------------------------------
__global__ void pack_vd(const unsigned char* __restrict__ pre,
                        const float* __restrict__ diff,
                        float* __restrict__ vd, int n2) {
    const int i32 = g_mask_i32;
    for (int i = blockIdx.x * blockDim.x + threadIdx.x; i < n2;
         i += gridDim.x * blockDim.x) {
        float2 d = ((const float2*)diff)[i];
        float v0, v1;
        valid2(pre, 2 * i, i32, v0, v1);
        float2 o;
        o.x = (v0 > 0.f) ? d.x : -1.f;
        o.y = (v1 > 0.f) ? d.y : -1.f;
        ((float2*)vd)[i] = o;
    }
}

// ---------------------------------------------------------------------------
// fp32 -> fp16 bulk convert, 3 segments in one launch
// ---------------------------------------------------------------------------
__global__ void cvt_all(const float4* __restrict__ s0, uint2* __restrict__ d0, int n0,
                        const float4* __restrict__ s1, uint2* __restrict__ d1, int n1,
                        const float4* __restrict__ s2, uint2* __restrict__ d2, int n2) {
    const int total = n0 + n1 + n2;
    for (int i = blockIdx.x * blockDim.x + threadIdx.x; i < total;
         i += gridDim.x * blockDim.x) {
        const float4* s; uint2* d; int j = i;
        if (j < n0)            { s = s0; d = d0; }
        else if (j - n0 < n1)  { s = s1; d = d1; j -= n0; }
        else                   { s = s2; d = d2; j -= n0 + n1; }
        float4 v = s[j];
        __half2 a = __floats2half2_rn(v.x, v.y);
        __half2 b = __floats2half2_rn(v.z, v.w);
        uint2 o;
        o.x = *(uint32_t*)&a;
        o.y = *(uint32_t*)&b;
        d[j] = o;
    }
}

// ---------------------------------------------------------------------------
// PTX helpers
// ---------------------------------------------------------------------------
__device__ __forceinline__ uint32_t smem_u32(const void* p) {
    uint32_t a;
    asm("{ .reg .u64 t; cvta.to.shared.u64 t, %1; cvt.u32.u64 %0, t; }"
        : "=r"(a) : "l"(p));
    return a;
}
#define CP_ASYNC16(dst, src) \
    asm volatile("cp.async.cg.shared.global [%0], [%1], 16;" \
                 :: "r"(dst), "l"(src) : "memory")
#define CP_COMMIT() asm volatile("cp.async.commit_group;" ::: "memory")
#define CP_WAIT0()  asm volatile("cp.async.wait_group 0;" ::: "memory")
#define CP_WAIT1()  asm volatile("cp.async.wait_group 1;" ::: "memory")

#define LDMATRIX_X4(r0, r1, r2, r3, addr) \
    asm volatile("ldmatrix.sync.aligned.m8n8.x4.shared.b16 {%0,%1,%2,%3}, [%4];" \
                 : "=r"(r0), "=r"(r1), "=r"(r2), "=r"(r3) : "r"(addr))
#define LDMATRIX_X4_T(r0, r1, r2, r3, addr) \
    asm volatile("ldmatrix.sync.aligned.m8n8.x4.trans.shared.b16 {%0,%1,%2,%3}, [%4];" \
                 : "=r"(r0), "=r"(r1), "=r"(r2), "=r"(r3) : "r"(addr))

#define MMA_F16(d, a0, a1, a2, a3, b0, b1)                                    \
    asm volatile(                                                             \
        "mma.sync.aligned.m16n8k16.row.col.f32.f16.f16.f32 "                  \
        "{%0,%1,%2,%3}, {%4,%5,%6,%7}, {%8,%9}, {%0,%1,%2,%3};"               \
        : "+f"((d)[0]), "+f"((d)[1]), "+f"((d)[2]), "+f"((d)[3])              \
        : "r"(a0), "r"(a1), "r"(a2), "r"(a3), "r"(b0), "r"(b1))

__device__ __forceinline__ uint32_t packh2(float a, float b) {
    __half2 h = __floats2half2_rn(a, b);
    return *(uint32_t*)&h;
}

// 64B-row swizzle (GEMM tiles: 32 halves/row)
__device__ __forceinline__ uint32_t swz(int r, int c) {
    return (uint32_t)(r * 64 + ((c ^ ((r >> 1) & 3)) << 4));
}
// 128B-row swizzle (attention tiles: 64 halves/row, 8 chunks)
__device__ __forceinline__ uint32_t swz128(int r, int c) {
    return (uint32_t)(r * 128 + ((c ^ (r & 7)) << 4));
}

// ---------------------------------------------------------------------------
// fp16 tensor-core GEMM, 128x128 CTA tile, 128 threads (2x2 warps of 64x64),
// 3-stage cp.async pipeline, one bar per k-iter, 2 CTAs/SM.
// MODE 0: merged QKV (1D grid, 4096 KV blocks then 512 remapped Q blocks,
//         fp16 out into qkv).  MODE 1: out-proj (2D grid, bias+post, fp32 out).
// ---------------------------------------------------------------------------
#define TBUF_B 8192                      // 128 rows * 64B (A or B)
#define GBUF_B (2 * TBUF_B)
#define GEMM_SMEM (3 * GBUF_B)           // 49152

template <int MODE>
__global__ __launch_bounds__(128, 2) void gemm_k(
    const __half* __restrict__ A, const __half* __restrict__ W,
    void* __restrict__ Cv,
    const float* __restrict__ bias, const unsigned char* __restrict__ post)
{
    extern __shared__ char smem[];
    const uint32_t sb = smem_u32(smem);
    const int tid  = threadIdx.x;
    const int lane = tid & 31;
    const int warp = tid >> 5;
    const int gid  = lane >> 2;
    const int tg   = lane & 3;
    const int wm   = warp >> 1;          // 0..1
    const int wn   = warp & 1;           // 0..1

    int bm, bn, colo, remap;
    float osc;
    const __half* B;
    int ldc;
    if (MODE == 0) {
        const int g0 = blockIdx.x;
        if (g0 < 4096) { bm = (g0 >> 3) * 128; bn = (g0 & 7) * 128;
                         B = W + 512 * 512; colo = 512; remap = 0; osc = 1.f; }
        else { const int g = g0 - 4096;
               bm = (g >> 2) * 128; bn = (g & 3) * 128;
               B = W; colo = 0; remap = 1; osc = 0.125f; }
        ldc = F3_;
    } else {
        bm = blockIdx.y * 128; bn = blockIdx.x * 128;
        B = W; colo = 0; remap = 0; osc = 1.f; ldc = EMB_;
    }

    float acc[4][8][4];
#pragma unroll
    for (int mi = 0; mi < 4; mi++)
#pragma unroll
        for (int ni = 0; ni < 8; ni++)
#pragma unroll
            for (int r = 0; r < 4; r++) acc[mi][ni][r] = 0.f;

    const int a_roff = (lane & 7) + ((lane >> 3) & 1) * 8;
    const int a_coff = lane >> 4;
    const int b_noff = (lane & 7) + (lane >> 4) * 8;
    const int b_coff = (lane >> 3) & 1;

#define ISSUE(kt, buf) do {                                                   \
        const uint32_t ab_ = sb + (buf) * GBUF_B;                             \
        const uint32_t bb_ = ab_ + TBUF_B;                                    \
        _Pragma("unroll")                                                     \
        for (int s = 0; s < 4; s++) {                                         \
            int idx = tid + s * 128;                                          \
            int r   = idx >> 2;                                               \
            int c   = idx & 3;                                                \
            int ga  = bm + r;                                                 \
            if (remap) ga = ((ga >> 7) << 9) | (ga & 127);                    \
            CP_ASYNC16(ab_ + swz(r, c),                                       \
                       &A[(size_t)ga * 512 + (kt) * 32 + c * 8]);             \
            CP_ASYNC16(bb_ + swz(r, c),                                       \
                       &B[(size_t)(bn + r) * 512 + (kt) * 32 + c * 8]);       \
        }                                                                     \
        CP_COMMIT();                                                          \
    } while (0)

    ISSUE(0, 0);
    ISSUE(1, 1);
    CP_WAIT1();
    __syncthreads();

#pragma unroll 1
    for (int kt = 0; kt < 16; kt++) {
        const uint32_t ab = sb + (kt % 3) * GBUF_B;
        const uint32_t bb = ab + TBUF_B;
#pragma unroll
        for (int ks = 0; ks < 2; ks++) {
            uint32_t af[4][4], bf[4][4];
#pragma unroll
            for (int mi = 0; mi < 4; mi++)
                LDMATRIX_X4(af[mi][0], af[mi][1], af[mi][2], af[mi][3],
                            ab + swz(wm * 64 + mi * 16 + a_roff,
                                     2 * ks + a_coff));
#pragma unroll
            for (int nj = 0; nj < 4; nj++)
                LDMATRIX_X4(bf[nj][0], bf[nj][1], bf[nj][2], bf[nj][3],
                            bb + swz(wn * 64 + nj * 16 + b_noff,
                                     2 * ks + b_coff));
#pragma unroll
            for (int mi = 0; mi < 4; mi++)
#pragma unroll
                for (int nj = 0; nj < 4; nj++) {
                    MMA_F16(acc[mi][2 * nj],
                            af[mi][0], af[mi][1], af[mi][2], af[mi][3],
                            bf[nj][0], bf[nj][1]);
                    MMA_F16(acc[mi][2 * nj + 1],
                            af[mi][0], af[mi][1], af[mi][2], af[mi][3],
                            bf[nj][2], bf[nj][3]);
                }
        }
        if (kt < 15) {
            if (kt + 2 < 16) { ISSUE(kt + 2, (kt + 2) % 3); CP_WAIT1(); }
            else             { CP_WAIT0(); }
            __syncthreads();
        }
    }
#undef ISSUE

    const int i32 = g_mask_i32;
#pragma unroll
    for (int mi = 0; mi < 4; mi++) {
        int rbase = bm + wm * 64 + mi * 16 + gid;
#pragma unroll
        for (int hf = 0; hf < 2; hf++) {
            int row  = rbase + hf * 8;
            int grow = remap ? (((row >> 7) << 9) | (row & 127)) : row;
            float keep = 1.f;
            if (MODE == 1) keep = (mask_at(post, grow, i32) == 0) ? 1.f : 0.f;
#pragma unroll
            for (int ni = 0; ni < 8; ni++) {
                int col = bn + wn * 64 + ni * 8 + 2 * tg;
                float v0 = acc[mi][ni][hf * 2 + 0] * osc;
                float v1 = acc[mi][ni][hf * 2 + 1] * osc;
                if (MODE == 1) {
                    v0 = (v0 + bias[col])     * keep;
                    v1 = (v1 + bias[col + 1]) * keep;
                    *(float2*)&((float*)Cv)[(size_t)grow * ldc + col] =
                        make_float2(v0, v1);
                } else {
                    __half2 hv = __floats2half2_rn(v0, v1);
                    *(__half2*)&((__half*)Cv)[(size_t)grow * ldc + colo + col]
                        = hv;
                }
            }
        }
    }
}

// ---------------------------------------------------------------------------
// Fused flash-style attention on tensor cores (validated R8/R9).
// CTA = (b, h), 128 thr (4 warps), warp owns 32 q rows. Q pre-scaled by 1/8.
// vd = valid? diff : -1.  3-stage KV pipeline, one bar per tile.
// w_i = e_i*d_i / (T + 1e-8*S)
// ---------------------------------------------------------------------------
#define ATT_SMEM (16384 + 3 * 8192 + 3 * 8192)   // 65536

__global__ __launch_bounds__(128, 2) void attn_mma(
    const __half* __restrict__ qkvh,
    const float* __restrict__ vd,
    __half* __restrict__ attn_h)
{
    extern __shared__ char dynsm[];
    const uint32_t qsb = smem_u32(dynsm);
    const uint32_t ksb = qsb + 16384;
    const uint32_t vsb = qsb + 16384 + 3 * 8192;

    const int b    = blockIdx.x;
    const int h    = blockIdx.y;
    const int tid  = threadIdx.x;
    const int lane = tid & 31;
    const int warp = tid >> 5;
    const int gid  = lane >> 2;
    const int tg   = lane & 3;

    const __half* qptr = qkvh + (size_t)b * 512 * F3_ + h * HD_;
    const __half* kptr = qptr + EMB_;
    const __half* vptr = qptr + 2 * EMB_;

    const int a_roff = (lane & 7) + ((lane >> 3) & 1) * 8;
    const int a_coff = lane >> 4;
    const int b_noff = (lane & 7) + (lane >> 4) * 8;
    const int b_coff = (lane >> 3) & 1;
    const int v_roff = lane & 15;
    const int v_coff = lane >> 4;

#define AT_ISSUE_KV(kt, buf) do {                                             \
        const uint32_t kb_ = ksb + (buf) * 8192;                              \
        const uint32_t vb_ = vsb + (buf) * 8192;                              \
        _Pragma("unroll")                                                     \
        for (int s = 0; s < 4; s++) {                                         \
            int r = (tid >> 3) + s * 16;                                      \
            int c = tid & 7;                                                  \
            size_t go = (size_t)((kt) * 64 + r) * F3_ + c * 8;                \
            CP_ASYNC16(kb_ + swz128(r, c), kptr + go);                        \
            CP_ASYNC16(vb_ + swz128(r, c), vptr + go);                        \
        }                                                                     \
        CP_COMMIT();                                                          \
    } while (0)

#pragma unroll
    for (int s = 0; s < 8; s++) {
        int r = (tid >> 3) + s * 16;
        int c = tid & 7;
        CP_ASYNC16(qsb + swz128(r, c), qptr + (size_t)r * F3_ + c * 8);
    }
    AT_ISSUE_KV(0, 0);
    AT_ISSUE_KV(1, 1);
    CP_WAIT1();
    __syncthreads();

    uint32_t qa[2][4][4];
#pragma unroll
    for (int m = 0; m < 2; m++)
#pragma unroll
        for (int ks = 0; ks < 4; ks++)
            LDMATRIX_X4(qa[m][ks][0], qa[m][ks][1], qa[m][ks][2], qa[m][ks][3],
                        qsb + swz128(warp * 32 + m * 16 + a_roff,
                                     2 * ks + a_coff));

    float oacc[2][8][4];
#pragma unroll
    for (int m = 0; m < 2; m++)
#pragma unroll
        for (int n = 0; n < 8; n++)
#pragma unroll
            for (int r = 0; r < 4; r++) oacc[m][n][r] = 0.f;
    float Ssum[2][2] = {{0.f, 0.f}, {0.f, 0.f}};
    float Tsum[2][2] = {{0.f, 0.f}, {0.f, 0.f}};

    const float* vdrow0 = vd + ((size_t)(b * NQ_ + warp * 32 + gid)) * NE_;

#pragma unroll 1
    for (int kt = 0; kt < 8; kt++) {
        const int buf = kt % 3;
        const uint32_t kb = ksb + buf * 8192;
        const uint32_t vb = vsb + buf * 8192;

        float lacc[2][8][4];
#pragma unroll
        for (int m = 0; m < 2; m++)
#pragma unroll
            for (int j = 0; j < 8; j++)
#pragma unroll
                for (int r = 0; r < 4; r++) lacc[m][j][r] = 0.f;

#pragma unroll
        for (int ks = 0; ks < 4; ks++) {
            uint32_t kf[4][4];
#pragma unroll
            for (int g = 0; g < 4; g++)
                LDMATRIX_X4(kf[g][0], kf[g][1], kf[g][2], kf[g][3],
                            kb + swz128(g * 16 + b_noff, 2 * ks + b_coff));
#pragma unroll
            for (int m = 0; m < 2; m++)
#pragma unroll
                for (int g = 0; g < 4; g++) {
                    MMA_F16(lacc[m][2 * g],
                            qa[m][ks][0], qa[m][ks][1], qa[m][ks][2], qa[m][ks][3],
                            kf[g][0], kf[g][1]);
                    MMA_F16(lacc[m][2 * g + 1],
                            qa[m][ks][0], qa[m][ks][1], qa[m][ks][2], qa[m][ks][3],
                            kf[g][2], kf[g][3]);
                }
        }

#pragma unroll
        for (int m = 0; m < 2; m++) {
            const float* vdp = vdrow0 + (size_t)m * 16 * NE_ + kt * 64 + tg * 2;
#pragma unroll
            for (int j = 0; j < 8; j++) {
                float2 d0 = *(const float2*)(vdp + j * 8);
                float2 d1 = *(const float2*)(vdp + 8 * NE_ + j * 8);
                float x0 = __expf(lacc[m][j][0]);
                float x1 = __expf(lacc[m][j][1]);
                float x2 = __expf(lacc[m][j][2]);
                float x3 = __expf(lacc[m][j][3]);
                float e0 = (d0.x >= 0.f) ? x0 : 0.f;
                float e1 = (d0.y >= 0.f) ? x1 : 0.f;
                float e2 = (d1.x >= 0.f) ? x2 : 0.f;
                float e3 = (d1.y >= 0.f) ? x3 : 0.f;
                float ed0 = x0 * fmaxf(d0.x, 0.f);
                float ed1 = x1 * fmaxf(d0.y, 0.f);
                float ed2 = x2 * fmaxf(d1.x, 0.f);
                float ed3 = x3 * fmaxf(d1.y, 0.f);
                Ssum[m][0] += e0 + e1;   Tsum[m][0] += ed0 + ed1;
                Ssum[m][1] += e2 + e3;   Tsum[m][1] += ed2 + ed3;
                lacc[m][j][0] = ed0; lacc[m][j][1] = ed1;
                lacc[m][j][2] = ed2; lacc[m][j][3] = ed3;
            }
        }

#pragma unroll
        for (int ks = 0; ks < 4; ks++) {
            uint32_t pa[2][4];
#pragma unroll
            for (int m = 0; m < 2; m++) {
                pa[m][0] = packh2(lacc[m][2 * ks][0],     lacc[m][2 * ks][1]);
                pa[m][1] = packh2(lacc[m][2 * ks][2],     lacc[m][2 * ks][3]);
                pa[m][2] = packh2(lacc[m][2 * ks + 1][0], lacc[m][2 * ks + 1][1]);
                pa[m][3] = packh2(lacc[m][2 * ks + 1][2], lacc[m][2 * ks + 1][3]);
            }
#pragma unroll
            for (int ng = 0; ng < 4; ng++) {
                uint32_t vf0, vf1, vf2, vf3;
                LDMATRIX_X4_T(vf0, vf1, vf2, vf3,
                              vb + swz128(ks * 16 + v_roff, 2 * ng + v_coff));
#pragma unroll
                for (int m = 0; m < 2; m++) {
                    MMA_F16(oacc[m][2 * ng],
                            pa[m][0], pa[m][1], pa[m][2], pa[m][3], vf0, vf1);
                    MMA_F16(oacc[m][2 * ng + 1],
                            pa[m][0], pa[m][1], pa[m][2], pa[m][3], vf2, vf3);
                }
            }
        }

        if (kt < 7) {
            if (kt + 2 < 8) { AT_ISSUE_KV(kt + 2, (kt + 2) % 3); CP_WAIT1(); }
            else            { CP_WAIT0(); }
            __syncthreads();
        }
    }
#undef AT_ISSUE_KV

#pragma unroll
    for (int m = 0; m < 2; m++)
#pragma unroll
        for (int hf = 0; hf < 2; hf++) {
            float s = Ssum[m][hf], t = Tsum[m][hf];
            s += __shfl_xor_sync(0xFFFFFFFFu, s, 1);
            s += __shfl_xor_sync(0xFFFFFFFFu, s, 2);
            t += __shfl_xor_sync(0xFFFFFFFFu, t, 1);
            t += __shfl_xor_sync(0xFFFFFFFFu, t, 2);
            float inv = (s > 0.f) ? (1.f / (t + 1e-8f * s)) : 0.f;
            const int q = warp * 32 + m * 16 + gid + hf * 8;
            __half* orow = &attn_h[((size_t)b * NQ_ + q) * EMB_ + h * HD_];
#pragma unroll
            for (int n = 0; n < 8; n++) {
                __half2 hv = __floats2half2_rn(oacc[m][n][hf * 2 + 0] * inv,
                                               oacc[m][n][hf * 2 + 1] * inv);
                *(__half2*)&orow[n * 8 + tg * 2] = hv;
            }
        }
}

// ---------------------------------------------------------------------------
// Launch
// ---------------------------------------------------------------------------
extern "C" void kernel_launch(void* const* d_in, const int* in_sizes, int n_in,
                              void* d_out, int out_size) {
    const float* entities     = (const float*)d_in[0];
    const unsigned char* pre  = (const unsigned char*)d_in[1];
    const float* diff         = (const float*)d_in[2];
    const unsigned char* post = (const unsigned char*)d_in[3];
    const float* W_in         = (const float*)d_in[4];
    const float* W_out        = (const float*)d_in[5];
    const float* b_out        = (const float*)d_in[6];
    float* out                = (float*)d_out;

    __half* qkvh   = nullptr;
    __half* ent_h  = nullptr;
    __half* win_h  = nullptr;
    __half* wout_h = nullptr;
    __half* attn_h = nullptr;
    float*  vd     = nullptr;
    cudaGetSymbolAddress((void**)&qkvh,   g_qkv_h);
    cudaGetSymbolAddress((void**)&ent_h,  g_ent_h);
    cudaGetSymbolAddress((void**)&win_h,  g_win_h);
    cudaGetSymbolAddress((void**)&wout_h, g_wout_h);
    cudaGetSymbolAddress((void**)&attn_h, g_attn_h);
    cudaGetSymbolAddress((void**)&vd,     g_vd);

    cudaFuncSetAttribute(gemm_k<0>, cudaFuncAttributeMaxDynamicSharedMemorySize,
                         GEMM_SMEM);
    cudaFuncSetAttribute(gemm_k<1>, cudaFuncAttributeMaxDynamicSharedMemorySize,
                         GEMM_SMEM);
    cudaFuncSetAttribute(attn_mma, cudaFuncAttributeMaxDynamicSharedMemorySize,
                         ATT_SMEM);

    detect_mask_kernel<<<1, 32>>>(pre);

    // fp32 -> fp16 conversions (one launch) + mask folding
    cvt_all<<<8192, 256>>>((const float4*)entities, (uint2*)ent_h,
                           (BS_ * NE_ * 512) / 4,
                           (const float4*)W_in, (uint2*)win_h,
                           (F3_ * 512) / 4,
                           (const float4*)W_out, (uint2*)wout_h,
                           (EMB_ * EMB_) / 4);
    pack_vd<<<4096, 256>>>(pre, diff, vd, (BS_ * NQ_ * NE_) / 2);

    // merged KV + Q projection (4096 KV blocks, then 512 remapped Q blocks)
    gemm_k<0><<<4608, 128, GEMM_SMEM>>>(ent_h, win_h, qkvh, nullptr, nullptr);

    // fused tensor-core attention -> half output
    attn_mma<<<dim3(BS_, H_), 128, ATT_SMEM>>>(qkvh, vd, attn_h);

    // out = attn @ W_out^T + b_out, post-masked (fp32 out)
    gemm_k<1><<<dim3(4, 128), 128, GEMM_SMEM>>>(attn_h, wout_h, out,
                                                b_out, post);
}